// round 1
// baseline (speedup 1.0000x reference)
#include <cuda_runtime.h>
#include <cstdint>

#define N_NODES 50000
#define N_EDGES 800000
#define HID 256
#define EMB 128

// ---------------- scratch (device globals; no runtime allocation) ----------------
__device__ int   g_is64;
__device__ int   g_deg[N_NODES];
__device__ int   g_rowptr[N_NODES + 1];
__device__ int   g_cursor[N_NODES];
__device__ int   g_csr_src[N_EDGES];
__device__ float g_csr_w[N_EDGES];
__device__ float g_agg[(size_t)N_NODES * HID];
__device__ float g_h1[(size_t)N_NODES * HID];

// ---------------- edge-index dtype probe (int64 vs int32) ----------------
// Reference declares int64, but JAX without x64 demotes to int32. If the data
// really is int64, every value read as long long is in [0, N_NODES). If it is
// int32, a long long read glues two random indices together and is almost
// surely out of range. Deterministic given the input buffer.
__global__ void probe_kernel(const void* ei) {
    __shared__ int ok;
    if (threadIdx.x == 0) ok = 1;
    __syncthreads();
    long long v = ((const long long*)ei)[threadIdx.x];  // in-bounds in both modes
    if (v < 0 || v >= (long long)N_NODES) atomicExch(&ok, 0);
    __syncthreads();
    if (threadIdx.x == 0) g_is64 = ok;
}

__device__ __forceinline__ int load_idx(const void* ei, long long pos) {
    return g_is64 ? (int)((const long long*)ei)[pos] : ((const int*)ei)[pos];
}

// ---------------- CSR build ----------------
__global__ void zero_kernel() {
    int i = blockIdx.x * blockDim.x + threadIdx.x;
    if (i < N_NODES) { g_deg[i] = 0; g_cursor[i] = 0; }
}

__global__ void hist_kernel(const void* ei) {
    int e = blockIdx.x * blockDim.x + threadIdx.x;
    if (e >= N_EDGES) return;
    int dst = load_idx(ei, (long long)N_EDGES + e);
    atomicAdd(&g_deg[dst], 1);
}

// single-block exclusive scan of g_deg -> g_rowptr
__global__ void scan_kernel() {
    __shared__ int s[1024];
    __shared__ int carry_s;
    int tid = threadIdx.x;
    if (tid == 0) carry_s = 0;
    __syncthreads();
    for (int base = 0; base < N_NODES; base += 1024) {
        int i = base + tid;
        int v = (i < N_NODES) ? g_deg[i] : 0;
        s[tid] = v;
        __syncthreads();
        // inclusive Hillis-Steele scan
        for (int off = 1; off < 1024; off <<= 1) {
            int t = (tid >= off) ? s[tid - off] : 0;
            __syncthreads();
            s[tid] += t;
            __syncthreads();
        }
        if (i < N_NODES) g_rowptr[i] = carry_s + s[tid] - v;  // exclusive
        __syncthreads();
        if (tid == 1023) carry_s += s[1023];
        __syncthreads();
    }
    if (tid == 0) g_rowptr[N_NODES] = carry_s;
}

__global__ void fill_kernel(const void* ei, const float* __restrict__ ew) {
    int e = blockIdx.x * blockDim.x + threadIdx.x;
    if (e >= N_EDGES) return;
    int src = load_idx(ei, e);
    int dst = load_idx(ei, (long long)N_EDGES + e);
    int p = g_rowptr[dst] + atomicAdd(&g_cursor[dst], 1);
    g_csr_src[p] = src;
    g_csr_w[p]   = ew[e];
}

// ---------------- aggregation: mean of w-scaled neighbor rows ----------------
// One warp per destination node. Each lane owns 8 of the 256 features
// (two float4's: [4*lane .. 4*lane+3] and [128+4*lane .. 128+4*lane+3]).
template <bool X_IS_H1>
__global__ void agg_kernel(const float* __restrict__ x_ext) {
    const float* __restrict__ x = X_IS_H1 ? g_h1 : x_ext;
    int gw   = (blockIdx.x * blockDim.x + threadIdx.x) >> 5;
    int lane = threadIdx.x & 31;
    if (gw >= N_NODES) return;
    int beg = g_rowptr[gw], end = g_rowptr[gw + 1];
    float4 a0 = make_float4(0.f, 0.f, 0.f, 0.f);
    float4 a1 = make_float4(0.f, 0.f, 0.f, 0.f);
    for (int i = beg; i < end; i++) {
        int   s = g_csr_src[i];
        float w = g_csr_w[i];
        const float4* r = (const float4*)(x + (size_t)s * HID);
        float4 v0 = r[lane];
        float4 v1 = r[lane + 32];
        a0.x += v0.x * w; a0.y += v0.y * w; a0.z += v0.z * w; a0.w += v0.w * w;
        a1.x += v1.x * w; a1.y += v1.y * w; a1.z += v1.z * w; a1.w += v1.w * w;
    }
    float inv = 1.0f / fmaxf((float)(end - beg), 1.0f);
    a0.x *= inv; a0.y *= inv; a0.z *= inv; a0.w *= inv;
    a1.x *= inv; a1.y *= inv; a1.z *= inv; a1.w *= inv;
    float4* o = (float4*)(g_agg + (size_t)gw * HID);
    o[lane]      = a0;
    o[lane + 32] = a1;
}

// ---------------- fused GEMM: Y = agg@Wl + X@Wr + b (+ReLU) ----------------
// Treated as one K=512 GEMM with the K axis split between (agg, Wl) and (X, Wr).
// 128x128 CTA tile, 8x8 per-thread microtile, BK=8.
template <int OUTN, bool RELU, bool X_IS_H1, bool Y_IS_H1>
__global__ void __launch_bounds__(256, 2)
gemm_fused(const float* __restrict__ x_ext,
           const float* __restrict__ Wl, const float* __restrict__ Wr,
           const float* __restrict__ bias, float* __restrict__ y_ext) {
    const float* __restrict__ A2 = X_IS_H1 ? g_h1 : x_ext;
    float* __restrict__ Y = Y_IS_H1 ? g_h1 : y_ext;

    constexpr int BM = 128, BN = 128, BK = 8;
    __shared__ float As[BK][BM + 4];
    __shared__ float Bs[BK][BN];

    int tid = threadIdx.x;          // 256 threads
    int tx = tid & 15;              // 16 cols of threads
    int ty = tid >> 4;              // 16 rows of threads
    int row0 = blockIdx.x * BM;
    int col0 = blockIdx.y * BN;

    float acc[8][8];
#pragma unroll
    for (int i = 0; i < 8; i++)
#pragma unroll
        for (int j = 0; j < 8; j++) acc[i][j] = 0.f;

    for (int kt = 0; kt < 2 * HID; kt += BK) {
        const float* __restrict__ A = (kt < HID) ? g_agg : A2;
        const float* __restrict__ B = (kt < HID) ? Wl : Wr;
        int ka = kt & (HID - 1);

        // load A tile: 128 rows x 8 k's; each thread one float4
        {
            int m  = tid >> 1;              // 0..127
            int kq = (tid & 1) * 4;         // 0 or 4
            int gr = row0 + m;
            float4 v = make_float4(0.f, 0.f, 0.f, 0.f);
            if (gr < N_NODES)
                v = *(const float4*)(A + (size_t)gr * HID + ka + kq);
            As[kq + 0][m] = v.x; As[kq + 1][m] = v.y;
            As[kq + 2][m] = v.z; As[kq + 3][m] = v.w;
        }
        // load B tile: 8 k's x 128 cols; 4 scalars per thread, coalesced
#pragma unroll
        for (int i = 0; i < 4; i++) {
            int l = tid + i * 256;
            int k = l >> 7, n = l & 127;
            Bs[k][n] = B[(size_t)(ka + k) * OUTN + col0 + n];
        }
        __syncthreads();

#pragma unroll
        for (int k = 0; k < BK; k++) {
            float a[8], b[8];
            *(float4*)&a[0] = *(const float4*)&As[k][ty * 8];
            *(float4*)&a[4] = *(const float4*)&As[k][ty * 8 + 4];
            *(float4*)&b[0] = *(const float4*)&Bs[k][tx * 8];
            *(float4*)&b[4] = *(const float4*)&Bs[k][tx * 8 + 4];
#pragma unroll
            for (int i = 0; i < 8; i++)
#pragma unroll
                for (int j = 0; j < 8; j++) acc[i][j] += a[i] * b[j];
        }
        __syncthreads();
    }

#pragma unroll
    for (int i = 0; i < 8; i++) {
        int r = row0 + ty * 8 + i;
        if (r >= N_NODES) continue;
#pragma unroll
        for (int j = 0; j < 8; j++) {
            int c = col0 + tx * 8 + j;
            float v = acc[i][j] + bias[c];
            if (RELU) v = fmaxf(v, 0.f);
            Y[(size_t)r * OUTN + c] = v;
        }
    }
}

// ---------------- launch ----------------
extern "C" void kernel_launch(void* const* d_in, const int* in_sizes, int n_in,
                              void* d_out, int out_size) {
    // inputs: node_ids(arange, unused), edge_index, edge_weight, emb,
    //         W1_l, W1_r, b1, W2_l, W2_r, b2
    const void*  ei  = d_in[1];
    const float* ew  = (const float*)d_in[2];
    const float* emb = (const float*)d_in[3];
    const float* W1l = (const float*)d_in[4];
    const float* W1r = (const float*)d_in[5];
    const float* b1  = (const float*)d_in[6];
    const float* W2l = (const float*)d_in[7];
    const float* W2r = (const float*)d_in[8];
    const float* b2  = (const float*)d_in[9];
    float* out = (float*)d_out;

    probe_kernel<<<1, 256>>>(ei);
    zero_kernel<<<(N_NODES + 255) / 256, 256>>>();
    hist_kernel<<<(N_EDGES + 255) / 256, 256>>>(ei);
    scan_kernel<<<1, 1024>>>();
    fill_kernel<<<(N_EDGES + 255) / 256, 256>>>(ei, ew);

    // layer 1: agg(emb) -> g_agg; h1 = relu(agg@W1l + emb@W1r + b1) -> g_h1
    agg_kernel<false><<<(N_NODES * 32 + 255) / 256, 256>>>(emb);
    {
        dim3 grid((N_NODES + 127) / 128, HID / 128);
        gemm_fused<HID, true, false, true><<<grid, 256>>>(emb, W1l, W1r, b1, nullptr);
    }

    // layer 2: agg(h1) -> g_agg; out = agg@W2l + h1@W2r + b2
    agg_kernel<true><<<(N_NODES * 32 + 255) / 256, 256>>>(nullptr);
    {
        dim3 grid((N_NODES + 127) / 128, EMB / 128);
        gemm_fused<EMB, false, true, false><<<grid, 256>>>(nullptr, W2l, W2r, b2, out);
    }
}

// round 3
// speedup vs baseline: 1.3205x; 1.3205x over previous
#include <cuda_runtime.h>
#include <cstdint>

#define N_NODES 50000
#define N_EDGES 800000
#define HID 256
#define EMB 128
#define SCAN_NB ((N_NODES + 1023) / 1024)   // 49

// ---------------- scratch (device globals; no runtime allocation) ----------------
__device__ int   g_is64;
__device__ int   g_deg[N_NODES];
__device__ int   g_rowptr[N_NODES + 1];
__device__ int   g_cursor[N_NODES];
__device__ int   g_bsum[SCAN_NB];
__device__ int   g_boff[SCAN_NB];
__device__ int   g_csr_src[N_EDGES];
__device__ float g_csr_w[N_EDGES];
__device__ float g_agg[(size_t)N_NODES * HID];
__device__ float g_h1[(size_t)N_NODES * HID];

// ---------------- edge-index dtype probe (int64 vs int32) ----------------
__global__ void probe_kernel(const void* ei) {
    __shared__ int ok;
    if (threadIdx.x == 0) ok = 1;
    __syncthreads();
    long long v = ((const long long*)ei)[threadIdx.x];
    if (v < 0 || v >= (long long)N_NODES) atomicExch(&ok, 0);
    __syncthreads();
    if (threadIdx.x == 0) g_is64 = ok;
}

__device__ __forceinline__ int load_idx(const void* ei, long long pos) {
    return g_is64 ? (int)((const long long*)ei)[pos] : ((const int*)ei)[pos];
}

// ---------------- CSR build ----------------
__global__ void zero_kernel() {
    int i = blockIdx.x * blockDim.x + threadIdx.x;
    if (i < N_NODES) { g_deg[i] = 0; g_cursor[i] = 0; }
}

__global__ void hist_kernel(const void* ei) {
    int e = blockIdx.x * blockDim.x + threadIdx.x;
    if (e >= N_EDGES) return;
    int dst = load_idx(ei, (long long)N_EDGES + e);
    atomicAdd(&g_deg[dst], 1);
}

// multi-block scan, stage 1: per-block exclusive scan + block sums
__global__ void scan_blocks() {
    __shared__ int wsum[32];
    int tid  = threadIdx.x;
    int lane = tid & 31, wid = tid >> 5;
    int i = blockIdx.x * 1024 + tid;
    int v = (i < N_NODES) ? g_deg[i] : 0;
    int x = v;
#pragma unroll
    for (int off = 1; off < 32; off <<= 1) {
        int t = __shfl_up_sync(0xffffffffu, x, off);
        if (lane >= off) x += t;
    }
    if (lane == 31) wsum[wid] = x;
    __syncthreads();
    if (wid == 0) {
        int s = wsum[lane];
#pragma unroll
        for (int off = 1; off < 32; off <<= 1) {
            int t = __shfl_up_sync(0xffffffffu, s, off);
            if (lane >= off) s += t;
        }
        wsum[lane] = s;
    }
    __syncthreads();
    int excl = x - v + ((wid > 0) ? wsum[wid - 1] : 0);
    if (i < N_NODES) g_rowptr[i] = excl;
    if (tid == 0) g_bsum[blockIdx.x] = wsum[31];
}

// stage 2: 1-block exclusive scan of block sums (SCAN_NB <= 64)
__global__ void scan_bsums() {
    __shared__ int s2[2];
    int tid = threadIdx.x, lane = tid & 31, wid = tid >> 5;
    int v = (tid < SCAN_NB) ? g_bsum[tid] : 0;
    int x = v;
#pragma unroll
    for (int off = 1; off < 32; off <<= 1) {
        int t = __shfl_up_sync(0xffffffffu, x, off);
        if (lane >= off) x += t;
    }
    if (lane == 31) s2[wid] = x;
    __syncthreads();
    int excl = x - v + ((wid > 0) ? s2[0] : 0);
    if (tid < SCAN_NB) g_boff[tid] = excl;
    if (tid == 0) g_rowptr[N_NODES] = N_EDGES;
}

// stage 3: add block offsets
__global__ void scan_add() {
    int i = blockIdx.x * 1024 + threadIdx.x;
    if (blockIdx.x > 0 && i < N_NODES) g_rowptr[i] += g_boff[blockIdx.x];
}

__global__ void fill_kernel(const void* ei, const float* __restrict__ ew) {
    int e = blockIdx.x * blockDim.x + threadIdx.x;
    if (e >= N_EDGES) return;
    int src = load_idx(ei, e);
    int dst = load_idx(ei, (long long)N_EDGES + e);
    int p = g_rowptr[dst] + atomicAdd(&g_cursor[dst], 1);
    g_csr_src[p] = src;
    g_csr_w[p]   = ew[e];
}

// ---------------- aggregation: mean of w-scaled neighbor rows ----------------
// One warp per destination node; 2-edge unroll to double outstanding gathers.
template <bool X_IS_H1>
__global__ void agg_kernel(const float* __restrict__ x_ext) {
    const float* __restrict__ x = X_IS_H1 ? g_h1 : x_ext;
    int gw   = (blockIdx.x * blockDim.x + threadIdx.x) >> 5;
    int lane = threadIdx.x & 31;
    if (gw >= N_NODES) return;
    int beg = g_rowptr[gw], end = g_rowptr[gw + 1];
    float4 a0 = make_float4(0.f, 0.f, 0.f, 0.f);
    float4 a1 = make_float4(0.f, 0.f, 0.f, 0.f);
    int i = beg;
    for (; i + 1 < end; i += 2) {
        int   s0 = g_csr_src[i],   s1 = g_csr_src[i + 1];
        float w0 = g_csr_w[i],     w1 = g_csr_w[i + 1];
        const float4* r0 = (const float4*)(x + (size_t)s0 * HID);
        const float4* r1 = (const float4*)(x + (size_t)s1 * HID);
        float4 u0 = r0[lane], u1 = r0[lane + 32];
        float4 v0 = r1[lane], v1 = r1[lane + 32];
        a0.x += u0.x * w0; a0.y += u0.y * w0; a0.z += u0.z * w0; a0.w += u0.w * w0;
        a1.x += u1.x * w0; a1.y += u1.y * w0; a1.z += u1.z * w0; a1.w += u1.w * w0;
        a0.x += v0.x * w1; a0.y += v0.y * w1; a0.z += v0.z * w1; a0.w += v0.w * w1;
        a1.x += v1.x * w1; a1.y += v1.y * w1; a1.z += v1.z * w1; a1.w += v1.w * w1;
    }
    if (i < end) {
        int   s = g_csr_src[i];
        float w = g_csr_w[i];
        const float4* r = (const float4*)(x + (size_t)s * HID);
        float4 u0 = r[lane], u1 = r[lane + 32];
        a0.x += u0.x * w; a0.y += u0.y * w; a0.z += u0.z * w; a0.w += u0.w * w;
        a1.x += u1.x * w; a1.y += u1.y * w; a1.z += u1.z * w; a1.w += u1.w * w;
    }
    float inv = 1.0f / fmaxf((float)(end - beg), 1.0f);
    a0.x *= inv; a0.y *= inv; a0.z *= inv; a0.w *= inv;
    a1.x *= inv; a1.y *= inv; a1.z *= inv; a1.w *= inv;
    float4* o = (float4*)(g_agg + (size_t)gw * HID);
    o[lane]      = a0;
    o[lane + 32] = a1;
}

// ---------------- fused GEMM: Y = agg@Wl + X@Wr + b (+ReLU) ----------------
// One K=512 GEMM, K split between (agg,Wl) and (X,Wr).
// 128x128 CTA tile, BK=16, double-buffered smem w/ register staging,
// 4+4 split microtile (conflict-free LDS.128 frags + float4 epilogue).
template <int OUTN, bool RELU, bool X_IS_H1, bool Y_IS_H1>
__global__ void __launch_bounds__(256, 2)
gemm_fused(const float* __restrict__ x_ext,
           const float* __restrict__ Wl, const float* __restrict__ Wr,
           const float* __restrict__ bias, float* __restrict__ y_ext) {
    const float* __restrict__ A2 = X_IS_H1 ? g_h1 : x_ext;
    float* __restrict__ Y = Y_IS_H1 ? g_h1 : y_ext;

    constexpr int BM = 128, BN = 128, BK = 16;
    constexpr int NT = (2 * HID) / BK;   // 32 k-tiles
    __shared__ float As[2][BK][BM + 4];
    __shared__ float Bs[2][BK][BN];

    int tid = threadIdx.x;
    int tx = tid & 15, ty = tid >> 4;
    int row0 = blockIdx.x * BM;
    int col0 = blockIdx.y * BN;

    // A staging: m = tid>>1 (0..127), kq = (tid&1)*8 (two float4 along k)
    int am  = tid >> 1;
    int akq = (tid & 1) * 8;
    bool avalid = (row0 + am) < N_NODES;
    // B staging: (k = tid>>5 and +8, n4 = tid&31)
    int bk = tid >> 5;
    int bn = (tid & 31) * 4;

    float acc[8][8];
#pragma unroll
    for (int i = 0; i < 8; i++)
#pragma unroll
        for (int j = 0; j < 8; j++) acc[i][j] = 0.f;

    float4 ar0, ar1, br0, br1;

    auto load_regs = [&](int t) {
        int kt = t * BK;
        const float* __restrict__ A = (kt < HID) ? g_agg : A2;
        const float* __restrict__ B = (kt < HID) ? Wl : Wr;
        int ka = kt & (HID - 1);
        if (avalid) {
            const float* ap = A + (size_t)(row0 + am) * HID + ka + akq;
            ar0 = *(const float4*)(ap);
            ar1 = *(const float4*)(ap + 4);
        } else {
            ar0 = make_float4(0.f, 0.f, 0.f, 0.f);
            ar1 = ar0;
        }
        br0 = *(const float4*)(B + (size_t)(ka + bk)     * OUTN + col0 + bn);
        br1 = *(const float4*)(B + (size_t)(ka + bk + 8) * OUTN + col0 + bn);
    };
    auto store_smem = [&](int buf) {
        As[buf][akq + 0][am] = ar0.x; As[buf][akq + 1][am] = ar0.y;
        As[buf][akq + 2][am] = ar0.z; As[buf][akq + 3][am] = ar0.w;
        As[buf][akq + 4][am] = ar1.x; As[buf][akq + 5][am] = ar1.y;
        As[buf][akq + 6][am] = ar1.z; As[buf][akq + 7][am] = ar1.w;
        *(float4*)&Bs[buf][bk][bn]     = br0;
        *(float4*)&Bs[buf][bk + 8][bn] = br1;
    };

    load_regs(0);
    store_smem(0);
    __syncthreads();

    for (int t = 0; t < NT; t++) {
        int buf = t & 1;
        if (t + 1 < NT) load_regs(t + 1);
#pragma unroll
        for (int k = 0; k < BK; k++) {
            float a[8], b[8];
            *(float4*)&a[0] = *(const float4*)&As[buf][k][ty * 4];
            *(float4*)&a[4] = *(const float4*)&As[buf][k][64 + ty * 4];
            *(float4*)&b[0] = *(const float4*)&Bs[buf][k][tx * 4];
            *(float4*)&b[4] = *(const float4*)&Bs[buf][k][64 + tx * 4];
#pragma unroll
            for (int i = 0; i < 8; i++)
#pragma unroll
                for (int j = 0; j < 8; j++) acc[i][j] += a[i] * b[j];
        }
        if (t + 1 < NT) {
            store_smem(1 - buf);
            __syncthreads();
        }
    }

    // epilogue: rows {ty*4+i, 64+ty*4+i}, cols {tx*4+j, 64+tx*4+j}; float4 stores
    float bl[4], bh[4];
#pragma unroll
    for (int j = 0; j < 4; j++) {
        bl[j] = bias[col0 + tx * 4 + j];
        bh[j] = bias[col0 + 64 + tx * 4 + j];
    }
#pragma unroll
    for (int i = 0; i < 8; i++) {
        int r = row0 + ((i < 4) ? (ty * 4 + i) : (64 + ty * 4 + i - 4));
        if (r >= N_NODES) continue;
        float4 vlo, vhi;
        float* pl = &vlo.x; float* ph = &vhi.x;
#pragma unroll
        for (int j = 0; j < 4; j++) {
            float v0 = acc[i][j]     + bl[j];
            float v1 = acc[i][j + 4] + bh[j];
            if (RELU) { v0 = fmaxf(v0, 0.f); v1 = fmaxf(v1, 0.f); }
            pl[j] = v0; ph[j] = v1;
        }
        *(float4*)(Y + (size_t)r * OUTN + col0 + tx * 4)      = vlo;
        *(float4*)(Y + (size_t)r * OUTN + col0 + 64 + tx * 4) = vhi;
    }
}

// ---------------- launch ----------------
extern "C" void kernel_launch(void* const* d_in, const int* in_sizes, int n_in,
                              void* d_out, int out_size) {
    const void*  ei  = d_in[1];
    const float* ew  = (const float*)d_in[2];
    const float* emb = (const float*)d_in[3];
    const float* W1l = (const float*)d_in[4];
    const float* W1r = (const float*)d_in[5];
    const float* b1  = (const float*)d_in[6];
    const float* W2l = (const float*)d_in[7];
    const float* W2r = (const float*)d_in[8];
    const float* b2  = (const float*)d_in[9];
    float* out = (float*)d_out;

    probe_kernel<<<1, 256>>>(ei);
    zero_kernel<<<(N_NODES + 255) / 256, 256>>>();
    hist_kernel<<<(N_EDGES + 255) / 256, 256>>>(ei);
    scan_blocks<<<SCAN_NB, 1024>>>();
    scan_bsums<<<1, 64>>>();
    scan_add<<<SCAN_NB, 1024>>>();
    fill_kernel<<<(N_EDGES + 255) / 256, 256>>>(ei, ew);

    // layer 1
    agg_kernel<false><<<(N_NODES * 32 + 255) / 256, 256>>>(emb);
    {
        dim3 grid((N_NODES + 127) / 128, HID / 128);
        gemm_fused<HID, true, false, true><<<grid, 256>>>(emb, W1l, W1r, b1, nullptr);
    }

    // layer 2
    agg_kernel<true><<<(N_NODES * 32 + 255) / 256, 256>>>(nullptr);
    {
        dim3 grid((N_NODES + 127) / 128, EMB / 128);
        gemm_fused<EMB, false, true, false><<<grid, 256>>>(nullptr, W2l, W2r, b2, out);
    }
}

// round 6
// speedup vs baseline: 2.1758x; 1.6477x over previous
#include <cuda_runtime.h>
#include <cuda_bf16.h>
#include <cstdint>

#define N_NODES 50000
#define N_EDGES 800000
#define HID 256
#define EMB 128
#define M_TILES 391                 // ceil(50000/128)
#define M_PAD (M_TILES * 128)       // 50048
#define SCAN_NB ((N_NODES + 1023) / 1024)   // 49

// ---------------- scratch (device globals; no runtime allocation) ----------------
__device__ int   g_is64;
__device__ int   g_deg[N_NODES];
__device__ int   g_rowptr[N_NODES + 1];
__device__ int   g_cursor[N_NODES];
__device__ int   g_bsum[SCAN_NB];
__device__ int   g_boff[SCAN_NB];
__device__ int   g_csr_src[N_EDGES];
__device__ float g_csr_w[N_EDGES];

// bf16 hi/lo split inputs (padded to M_PAD rows; pad stays zero from BSS init)
__device__ __nv_bfloat16 g_A1hi[(size_t)M_PAD * HID];
__device__ __nv_bfloat16 g_A1lo[(size_t)M_PAD * HID];
__device__ __nv_bfloat16 g_h1hi[(size_t)M_PAD * HID];
__device__ __nv_bfloat16 g_h1lo[(size_t)M_PAD * HID];
// transposed weights [N,K] bf16 hi/lo
__device__ __nv_bfloat16 g_Wt1hi[512 * 256];
__device__ __nv_bfloat16 g_Wt1lo[512 * 256];
__device__ __nv_bfloat16 g_Wt2hi[256 * 256];
__device__ __nv_bfloat16 g_Wt2lo[256 * 256];
// GEMM outputs
__device__ float g_T1l[(size_t)N_NODES * HID];
__device__ float g_T1r[(size_t)N_NODES * HID];
__device__ float g_T2l[(size_t)N_NODES * EMB];
__device__ float g_T2r[(size_t)N_NODES * EMB];

// ---------------- PTX helpers (sm_80-era only: cp.async, ldmatrix, mma.sync) ----------------
__device__ __forceinline__ uint32_t smem_u32(const void* p) {
    uint32_t r;
    asm("{ .reg .u64 t; cvta.to.shared.u64 t, %1; cvt.u32.u64 %0, t; }" : "=r"(r) : "l"(p));
    return r;
}
__device__ __forceinline__ void cpa16(uint32_t dst, const void* src) {
    asm volatile("cp.async.cg.shared.global [%0], [%1], 16;" :: "r"(dst), "l"(src));
}
#define CP_COMMIT() asm volatile("cp.async.commit_group;" ::: "memory")
#define CP_WAIT(n)  asm volatile("cp.async.wait_group %0;" :: "n"(n) : "memory")

__device__ __forceinline__ void ldmx4(uint32_t* d, uint32_t addr) {
    asm volatile("ldmatrix.sync.aligned.m8n8.x4.shared.b16 {%0,%1,%2,%3}, [%4];"
                 : "=r"(d[0]), "=r"(d[1]), "=r"(d[2]), "=r"(d[3]) : "r"(addr));
}
__device__ __forceinline__ void mma16816(float* C, const uint32_t* A, uint32_t b0, uint32_t b1) {
    asm volatile(
        "mma.sync.aligned.m16n8k16.row.col.f32.bf16.bf16.f32 "
        "{%0,%1,%2,%3}, {%4,%5,%6,%7}, {%8,%9}, {%0,%1,%2,%3};"
        : "+f"(C[0]), "+f"(C[1]), "+f"(C[2]), "+f"(C[3])
        : "r"(A[0]), "r"(A[1]), "r"(A[2]), "r"(A[3]), "r"(b0), "r"(b1));
}
#define SW128(x) ((x) ^ (((x) >> 3) & 0x70))

// ---------------- edge-index dtype probe ----------------
__global__ void probe_kernel(const void* ei) {
    __shared__ int ok;
    if (threadIdx.x == 0) ok = 1;
    __syncthreads();
    long long v = ((const long long*)ei)[threadIdx.x];
    if (v < 0 || v >= (long long)N_NODES) atomicExch(&ok, 0);
    __syncthreads();
    if (threadIdx.x == 0) g_is64 = ok;
}
__device__ __forceinline__ int load_idx(const void* ei, long long pos) {
    return g_is64 ? (int)((const long long*)ei)[pos] : ((const int*)ei)[pos];
}

// ---------------- CSR build ----------------
__global__ void zero_kernel() {
    int i = blockIdx.x * blockDim.x + threadIdx.x;
    if (i < N_NODES) { g_deg[i] = 0; g_cursor[i] = 0; }
}
__global__ void hist_kernel(const void* ei) {
    int e = blockIdx.x * blockDim.x + threadIdx.x;
    if (e >= N_EDGES) return;
    atomicAdd(&g_deg[load_idx(ei, (long long)N_EDGES + e)], 1);
}
__global__ void scan_blocks() {
    __shared__ int wsum[32];
    int tid = threadIdx.x, lane = tid & 31, wid = tid >> 5;
    int i = blockIdx.x * 1024 + tid;
    int v = (i < N_NODES) ? g_deg[i] : 0;
    int x = v;
#pragma unroll
    for (int off = 1; off < 32; off <<= 1) {
        int t = __shfl_up_sync(0xffffffffu, x, off);
        if (lane >= off) x += t;
    }
    if (lane == 31) wsum[wid] = x;
    __syncthreads();
    if (wid == 0) {
        int s = wsum[lane];
#pragma unroll
        for (int off = 1; off < 32; off <<= 1) {
            int t = __shfl_up_sync(0xffffffffu, s, off);
            if (lane >= off) s += t;
        }
        wsum[lane] = s;
    }
    __syncthreads();
    int excl = x - v + ((wid > 0) ? wsum[wid - 1] : 0);
    if (i < N_NODES) g_rowptr[i] = excl;
    if (tid == 0) g_bsum[blockIdx.x] = wsum[31];
}
__global__ void scan_bsums() {
    __shared__ int s2[2];
    int tid = threadIdx.x, lane = tid & 31, wid = tid >> 5;
    int v = (tid < SCAN_NB) ? g_bsum[tid] : 0;
    int x = v;
#pragma unroll
    for (int off = 1; off < 32; off <<= 1) {
        int t = __shfl_up_sync(0xffffffffu, x, off);
        if (lane >= off) x += t;
    }
    if (lane == 31) s2[wid] = x;
    __syncthreads();
    int excl = x - v + ((wid > 0) ? s2[0] : 0);
    if (tid < SCAN_NB) g_boff[tid] = excl;
    if (tid == 0) g_rowptr[N_NODES] = N_EDGES;
}
__global__ void scan_add() {
    int i = blockIdx.x * 1024 + threadIdx.x;
    if (blockIdx.x > 0 && i < N_NODES) g_rowptr[i] += g_boff[blockIdx.x];
}
__global__ void fill_kernel(const void* ei, const float* __restrict__ ew) {
    int e = blockIdx.x * blockDim.x + threadIdx.x;
    if (e >= N_EDGES) return;
    int src = load_idx(ei, e);
    int dst = load_idx(ei, (long long)N_EDGES + e);
    int p = g_rowptr[dst] + atomicAdd(&g_cursor[dst], 1);
    g_csr_src[p] = src;
    g_csr_w[p]   = ew[e];
}

// ---------------- fp32 -> bf16 hi/lo split of emb ----------------
__global__ void conv_hilo(const float* __restrict__ x) {
    int i = blockIdx.x * blockDim.x + threadIdx.x;      // over N_NODES*HID/4
    if (i >= N_NODES * HID / 4) return;
    float4 v = ((const float4*)x)[i];
    float f[4] = {v.x, v.y, v.z, v.w};
    __align__(8) __nv_bfloat16 h[4], l[4];
#pragma unroll
    for (int j = 0; j < 4; j++) {
        h[j] = __float2bfloat16_rn(f[j]);
        l[j] = __float2bfloat16_rn(f[j] - __bfloat162float(h[j]));
    }
    ((uint2*)g_A1hi)[i] = *(uint2*)h;
    ((uint2*)g_A1lo)[i] = *(uint2*)l;
}

// ---------------- weight transpose + split: Wt[n][k] = W[k][n] ----------------
template <int LAYER>
__global__ void conv_wt(const float* __restrict__ Wa, const float* __restrict__ Wb) {
    constexpr int NTOT = (LAYER == 1) ? 512 : 256;
    constexpr int NH   = (LAYER == 1) ? 256 : 128;
    __nv_bfloat16* thi = (LAYER == 1) ? g_Wt1hi : g_Wt2hi;
    __nv_bfloat16* tlo = (LAYER == 1) ? g_Wt1lo : g_Wt2lo;
    int idx = blockIdx.x * blockDim.x + threadIdx.x;    // over NTOT*256
    if (idx >= NTOT * 256) return;
    int n = idx >> 8, k = idx & 255;
    float v = (n < NH) ? Wa[(size_t)k * NH + n] : Wb[(size_t)k * NH + (n - NH)];
    __nv_bfloat16 h = __float2bfloat16_rn(v);
    thi[idx] = h;
    tlo[idx] = __float2bfloat16_rn(v - __bfloat162float(h));
}

// ---------------- mma.sync bf16 split GEMM ----------------
// D[row0:+128][bn0:+128] = A[.,256] @ Wt[bn0:+128, 256]^T  via hi*hi+hi*lo+lo*hi
// CTA 128x128, 8 warps (warp tile 64x32), K-chunks of 32, cp.async double buffer.
// smem per buffer: Ahi|Alo|Bhi|Blo, each 128 rows x 32 bf16 (SW128 on 64B rows).
#define GBUF 32768
#define GSM_TOTAL (2 * GBUF)

template <int LAYER>
__global__ void __launch_bounds__(256, 1) gemm_mma() {
    const __nv_bfloat16* __restrict__ Ahi = (LAYER == 1) ? g_A1hi : g_h1hi;
    const __nv_bfloat16* __restrict__ Alo = (LAYER == 1) ? g_A1lo : g_h1lo;
    const __nv_bfloat16* __restrict__ Bhi = (LAYER == 1) ? g_Wt1hi : g_Wt2hi;
    const __nv_bfloat16* __restrict__ Blo = (LAYER == 1) ? g_Wt1lo : g_Wt2lo;

    const int bn0 = blockIdx.y * 128;
    float* __restrict__ out;
    int ostride, ocol0;
    if (LAYER == 1) {
        out = (bn0 < 256) ? g_T1l : g_T1r;
        ostride = 256; ocol0 = bn0 & 255;
    } else {
        out = (bn0 == 0) ? g_T2l : g_T2r;
        ostride = 128; ocol0 = 0;
    }

    extern __shared__ char smem[];
    uint32_t sb = smem_u32(smem);
    int tid = threadIdx.x, wid = tid >> 5, lane = tid & 31;
    int wm = (wid & 1) * 64, wn = (wid >> 1) * 32;
    int row0 = blockIdx.x * 128;

    float acc[4][4][4];
#pragma unroll
    for (int a = 0; a < 4; a++)
#pragma unroll
        for (int b = 0; b < 4; b++)
#pragma unroll
            for (int c = 0; c < 4; c++) acc[a][b][c] = 0.f;

    auto issue = [&](int kc) {
        uint32_t bb = sb + (uint32_t)(kc & 1) * GBUF;
#pragma unroll
        for (int i = 0; i < 2; i++) {
            int u = tid + i * 256;          // 0..511
            int r = u >> 2, c4 = u & 3;
            uint32_t d = SW128((uint32_t)(r * 64 + c4 * 16));
            size_t goA = (size_t)(row0 + r) * 256 + kc * 32 + c4 * 8;
            size_t goB = (size_t)(bn0 + r) * 256 + kc * 32 + c4 * 8;
            cpa16(bb + d,          Ahi + goA);
            cpa16(bb + 8192 + d,   Alo + goA);
            cpa16(bb + 16384 + d,  Bhi + goB);
            cpa16(bb + 24576 + d,  Blo + goB);
        }
        CP_COMMIT();
    };

    // ldmatrix lane geometry (shared by A and B tiles)
    int lrow8 = ((lane >> 3) & 1) * 8 + (lane & 7);   // row within 16-row frag
    int lkoff = (lane >> 4);                          // 0/1 -> k chunk +0/+8

    issue(0);
    for (int kc = 0; kc < 8; kc++) {
        if (kc + 1 < 8) { issue(kc + 1); CP_WAIT(1); } else { CP_WAIT(0); }
        __syncthreads();
        uint32_t bb = sb + (uint32_t)(kc & 1) * GBUF;
        uint32_t aH = bb, aL = bb + 8192, bH = bb + 16384, bL = bb + 24576;
#pragma unroll
        for (int k16 = 0; k16 < 2; k16++) {
            uint32_t ah[4][4], al[4][4], bh[2][4], bl[2][4];
#pragma unroll
            for (int fm = 0; fm < 4; fm++) {
                int row = wm + fm * 16 + lrow8;
                uint32_t ad = SW128((uint32_t)(row * 64 + (k16 * 2 + lkoff) * 16));
                ldmx4(ah[fm], aH + ad);
                ldmx4(al[fm], aL + ad);
            }
#pragma unroll
            for (int g = 0; g < 2; g++) {
                int row = wn + g * 16 + lrow8;
                uint32_t bd = SW128((uint32_t)(row * 64 + (k16 * 2 + lkoff) * 16));
                ldmx4(bh[g], bH + bd);
                ldmx4(bl[g], bL + bd);
            }
#pragma unroll
            for (int fm = 0; fm < 4; fm++)
#pragma unroll
                for (int fn = 0; fn < 4; fn++) {
                    int g = fn >> 1, p = fn & 1;
                    mma16816(acc[fm][fn], ah[fm], bh[g][p], bh[g][p + 2]);  // hi*hi
                    mma16816(acc[fm][fn], ah[fm], bl[g][p], bl[g][p + 2]);  // hi*lo
                    mma16816(acc[fm][fn], al[fm], bh[g][p], bh[g][p + 2]);  // lo*hi
                }
        }
        __syncthreads();
    }

    // epilogue: acc[fm][fn] = {(r,c),(r,c+1),(r+8,c),(r+8,c+1)}
#pragma unroll
    for (int fm = 0; fm < 4; fm++) {
        int r = row0 + wm + fm * 16 + (lane >> 2);
#pragma unroll
        for (int fn = 0; fn < 4; fn++) {
            int c = ocol0 + wn + fn * 8 + (lane & 3) * 2;
            if (r < N_NODES)
                *(float2*)(out + (size_t)r * ostride + c) =
                    make_float2(acc[fm][fn][0], acc[fm][fn][1]);
            if (r + 8 < N_NODES)
                *(float2*)(out + (size_t)(r + 8) * ostride + c) =
                    make_float2(acc[fm][fn][2], acc[fm][fn][3]);
        }
    }
}

// ---------------- AGG1: h1 = relu(meanagg(T1l) + T1r + b1) -> bf16 hi/lo ----------------
__device__ __forceinline__ void split_store4(__nv_bfloat16* hi, __nv_bfloat16* lo, float4 v) {
    float f[4] = {v.x, v.y, v.z, v.w};
    __align__(8) __nv_bfloat16 h[4], l[4];
#pragma unroll
    for (int i = 0; i < 4; i++) {
        h[i] = __float2bfloat16_rn(f[i]);
        l[i] = __float2bfloat16_rn(f[i] - __bfloat162float(h[i]));
    }
    *(uint2*)hi = *(uint2*)h;
    *(uint2*)lo = *(uint2*)l;
}

__global__ void agg1_kernel(const float* __restrict__ b1) {
    int gw = (blockIdx.x * blockDim.x + threadIdx.x) >> 5;
    int lane = threadIdx.x & 31;
    if (gw >= N_NODES) return;
    int beg = g_rowptr[gw], end = g_rowptr[gw + 1];
    float4 a0 = make_float4(0.f, 0.f, 0.f, 0.f);
    float4 a1 = make_float4(0.f, 0.f, 0.f, 0.f);
    int i = beg;
    for (; i + 1 < end; i += 2) {
        int   s0 = g_csr_src[i], s1 = g_csr_src[i + 1];
        float w0 = g_csr_w[i],   w1 = g_csr_w[i + 1];
        const float4* r0 = (const float4*)(g_T1l + (size_t)s0 * HID);
        const float4* r1 = (const float4*)(g_T1l + (size_t)s1 * HID);
        float4 u0 = r0[lane], u1 = r0[lane + 32];
        float4 v0 = r1[lane], v1 = r1[lane + 32];
        a0.x += u0.x * w0; a0.y += u0.y * w0; a0.z += u0.z * w0; a0.w += u0.w * w0;
        a1.x += u1.x * w0; a1.y += u1.y * w0; a1.z += u1.z * w0; a1.w += u1.w * w0;
        a0.x += v0.x * w1; a0.y += v0.y * w1; a0.z += v0.z * w1; a0.w += v0.w * w1;
        a1.x += v1.x * w1; a1.y += v1.y * w1; a1.z += v1.z * w1; a1.w += v1.w * w1;
    }
    if (i < end) {
        int   s = g_csr_src[i];
        float w = g_csr_w[i];
        const float4* r = (const float4*)(g_T1l + (size_t)s * HID);
        float4 u0 = r[lane], u1 = r[lane + 32];
        a0.x += u0.x * w; a0.y += u0.y * w; a0.z += u0.z * w; a0.w += u0.w * w;
        a1.x += u1.x * w; a1.y += u1.y * w; a1.z += u1.z * w; a1.w += u1.w * w;
    }
    float inv = 1.0f / fmaxf((float)(end - beg), 1.0f);
    const float4* tr = (const float4*)(g_T1r + (size_t)gw * HID);
    float4 t0 = tr[lane], t1 = tr[lane + 32];
    const float4* bb = (const float4*)b1;
    float4 c0 = bb[lane], c1 = bb[lane + 32];
    float4 o0, o1;
    o0.x = fmaxf(a0.x * inv + t0.x + c0.x, 0.f);
    o0.y = fmaxf(a0.y * inv + t0.y + c0.y, 0.f);
    o0.z = fmaxf(a0.z * inv + t0.z + c0.z, 0.f);
    o0.w = fmaxf(a0.w * inv + t0.w + c0.w, 0.f);
    o1.x = fmaxf(a1.x * inv + t1.x + c1.x, 0.f);
    o1.y = fmaxf(a1.y * inv + t1.y + c1.y, 0.f);
    o1.z = fmaxf(a1.z * inv + t1.z + c1.z, 0.f);
    o1.w = fmaxf(a1.w * inv + t1.w + c1.w, 0.f);
    split_store4(g_h1hi + (size_t)gw * HID + lane * 4,
                 g_h1lo + (size_t)gw * HID + lane * 4, o0);
    split_store4(g_h1hi + (size_t)gw * HID + 128 + lane * 4,
                 g_h1lo + (size_t)gw * HID + 128 + lane * 4, o1);
}

// ---------------- AGG2: out = meanagg(T2l) + T2r + b2 ----------------
__global__ void agg2_kernel(const float* __restrict__ b2, float* __restrict__ out) {
    int gw = (blockIdx.x * blockDim.x + threadIdx.x) >> 5;
    int lane = threadIdx.x & 31;
    if (gw >= N_NODES) return;
    int beg = g_rowptr[gw], end = g_rowptr[gw + 1];
    float4 a = make_float4(0.f, 0.f, 0.f, 0.f);
    int i = beg;
    for (; i + 3 < end; i += 4) {
        int s0 = g_csr_src[i], s1 = g_csr_src[i + 1], s2 = g_csr_src[i + 2], s3 = g_csr_src[i + 3];
        float w0 = g_csr_w[i], w1 = g_csr_w[i + 1], w2 = g_csr_w[i + 2], w3 = g_csr_w[i + 3];
        float4 u0 = ((const float4*)(g_T2l + (size_t)s0 * EMB))[lane];
        float4 u1 = ((const float4*)(g_T2l + (size_t)s1 * EMB))[lane];
        float4 u2 = ((const float4*)(g_T2l + (size_t)s2 * EMB))[lane];
        float4 u3 = ((const float4*)(g_T2l + (size_t)s3 * EMB))[lane];
        a.x += u0.x * w0 + u1.x * w1 + u2.x * w2 + u3.x * w3;
        a.y += u0.y * w0 + u1.y * w1 + u2.y * w2 + u3.y * w3;
        a.z += u0.z * w0 + u1.z * w1 + u2.z * w2 + u3.z * w3;
        a.w += u0.w * w0 + u1.w * w1 + u2.w * w2 + u3.w * w3;
    }
    for (; i < end; i++) {
        int s = g_csr_src[i];
        float w = g_csr_w[i];
        float4 u = ((const float4*)(g_T2l + (size_t)s * EMB))[lane];
        a.x += u.x * w; a.y += u.y * w; a.z += u.z * w; a.w += u.w * w;
    }
    float inv = 1.0f / fmaxf((float)(end - beg), 1.0f);
    float4 t = ((const float4*)(g_T2r + (size_t)gw * EMB))[lane];
    float4 c = ((const float4*)b2)[lane];
    float4 o;
    o.x = a.x * inv + t.x + c.x;
    o.y = a.y * inv + t.y + c.y;
    o.z = a.z * inv + t.z + c.z;
    o.w = a.w * inv + t.w + c.w;
    ((float4*)(out + (size_t)gw * EMB))[lane] = o;
}

// ---------------- launch ----------------
extern "C" void kernel_launch(void* const* d_in, const int* in_sizes, int n_in,
                              void* d_out, int out_size) {
    const void*  ei  = d_in[1];
    const float* ew  = (const float*)d_in[2];
    const float* emb = (const float*)d_in[3];
    const float* W1l = (const float*)d_in[4];
    const float* W1r = (const float*)d_in[5];
    const float* b1  = (const float*)d_in[6];
    const float* W2l = (const float*)d_in[7];
    const float* W2r = (const float*)d_in[8];
    const float* b2  = (const float*)d_in[9];
    float* out = (float*)d_out;

    static bool attr_done = false;
    if (!attr_done) {
        cudaFuncSetAttribute(gemm_mma<1>, cudaFuncAttributeMaxDynamicSharedMemorySize, GSM_TOTAL);
        cudaFuncSetAttribute(gemm_mma<2>, cudaFuncAttributeMaxDynamicSharedMemorySize, GSM_TOTAL);
        attr_done = true;
    }

    // CSR build
    probe_kernel<<<1, 256>>>(ei);
    zero_kernel<<<(N_NODES + 255) / 256, 256>>>();
    hist_kernel<<<(N_EDGES + 255) / 256, 256>>>(ei);
    scan_blocks<<<SCAN_NB, 1024>>>();
    scan_bsums<<<1, 64>>>();
    scan_add<<<SCAN_NB, 1024>>>();
    fill_kernel<<<(N_EDGES + 255) / 256, 256>>>(ei, ew);

    // conversions
    conv_hilo<<<(N_NODES * HID / 4 + 255) / 256, 256>>>(emb);
    conv_wt<1><<<(512 * 256 + 255) / 256, 256>>>(W1l, W1r);
    conv_wt<2><<<(256 * 256 + 255) / 256, 256>>>(W2l, W2r);

    // layer 1: T1 = emb @ [W1l | W1r]   (grid y: tiles 0,1 -> T1l; 2,3 -> T1r)
    { dim3 g(M_TILES, 4); gemm_mma<1><<<g, 256, GSM_TOTAL>>>(); }
    // h1 = relu(agg(T1l) + T1r + b1)   (bf16 hi/lo output)
    agg1_kernel<<<(N_NODES * 32 + 255) / 256, 256>>>(b1);

    // layer 2: T2 = h1 @ [W2l | W2r]   (grid y: tile 0 -> T2l; 1 -> T2r)
    { dim3 g(M_TILES, 2); gemm_mma<2><<<g, 256, GSM_TOTAL>>>(); }
    // out = agg(T2l) + T2r + b2
    agg2_kernel<<<(N_NODES * 32 + 255) / 256, 256>>>(b2, out);
}

// round 7
// speedup vs baseline: 2.2783x; 1.0471x over previous
#include <cuda_runtime.h>
#include <cuda_bf16.h>
#include <cstdint>

#define N_NODES 50000
#define N_EDGES 800000
#define HID 256
#define EMB 128
#define M_TILES 391                 // ceil(50000/128)
#define M_PAD (M_TILES * 128)       // 50048
#define SCAN_NB ((N_NODES + 1023) / 1024)   // 49

// ---------------- scratch (device globals; no runtime allocation) ----------------
__device__ int   g_is64;
__device__ int   g_deg[N_NODES];
__device__ int   g_rowptr[N_NODES + 1];
__device__ int   g_cursor[N_NODES];
__device__ int   g_bsum[SCAN_NB];
__device__ int   g_boff[SCAN_NB];
__device__ int   g_csr_src[N_EDGES];
__device__ float g_csr_w[N_EDGES];

// bf16 hi/lo split inputs (padded to M_PAD rows; pad stays zero from BSS init)
__device__ __nv_bfloat16 g_A1hi[(size_t)M_PAD * HID];
__device__ __nv_bfloat16 g_A1lo[(size_t)M_PAD * HID];
__device__ __nv_bfloat16 g_h1hi[(size_t)M_PAD * HID];
__device__ __nv_bfloat16 g_h1lo[(size_t)M_PAD * HID];
// transposed weights [N,K] bf16 hi/lo
__device__ __nv_bfloat16 g_Wt1hi[512 * 256];
__device__ __nv_bfloat16 g_Wt1lo[512 * 256];
__device__ __nv_bfloat16 g_Wt2hi[256 * 256];
__device__ __nv_bfloat16 g_Wt2lo[256 * 256];
// GEMM outputs
__device__ float g_T1l[(size_t)N_NODES * HID];
__device__ float g_T1r[(size_t)N_NODES * HID];
__device__ float g_T2l[(size_t)N_NODES * EMB];
__device__ float g_T2r[(size_t)N_NODES * EMB];

// ---------------- PTX helpers (sm_80-era only: cp.async, ldmatrix, mma.sync) ----------------
__device__ __forceinline__ uint32_t smem_u32(const void* p) {
    uint32_t r;
    asm("{ .reg .u64 t; cvta.to.shared.u64 t, %1; cvt.u32.u64 %0, t; }" : "=r"(r) : "l"(p));
    return r;
}
__device__ __forceinline__ void cpa16(uint32_t dst, const void* src) {
    asm volatile("cp.async.cg.shared.global [%0], [%1], 16;" :: "r"(dst), "l"(src));
}
#define CP_COMMIT() asm volatile("cp.async.commit_group;" ::: "memory")
#define CP_WAIT(n)  asm volatile("cp.async.wait_group %0;" :: "n"(n) : "memory")

__device__ __forceinline__ void ldmx4(uint32_t* d, uint32_t addr) {
    asm volatile("ldmatrix.sync.aligned.m8n8.x4.shared.b16 {%0,%1,%2,%3}, [%4];"
                 : "=r"(d[0]), "=r"(d[1]), "=r"(d[2]), "=r"(d[3]) : "r"(addr));
}
__device__ __forceinline__ void mma16816(float* C, const uint32_t* A, uint32_t b0, uint32_t b1) {
    asm volatile(
        "mma.sync.aligned.m16n8k16.row.col.f32.bf16.bf16.f32 "
        "{%0,%1,%2,%3}, {%4,%5,%6,%7}, {%8,%9}, {%0,%1,%2,%3};"
        : "+f"(C[0]), "+f"(C[1]), "+f"(C[2]), "+f"(C[3])
        : "r"(A[0]), "r"(A[1]), "r"(A[2]), "r"(A[3]), "r"(b0), "r"(b1));
}
#define SW128(x) ((x) ^ (((x) >> 3) & 0x70))

// ---------------- edge-index dtype probe ----------------
__global__ void probe_kernel(const void* ei) {
    __shared__ int ok;
    if (threadIdx.x == 0) ok = 1;
    __syncthreads();
    long long v = ((const long long*)ei)[threadIdx.x];
    if (v < 0 || v >= (long long)N_NODES) atomicExch(&ok, 0);
    __syncthreads();
    if (threadIdx.x == 0) g_is64 = ok;
}
__device__ __forceinline__ int load_idx(const void* ei, long long pos) {
    return g_is64 ? (int)((const long long*)ei)[pos] : ((const int*)ei)[pos];
}

// ---------------- CSR build ----------------
__global__ void zero_kernel() {
    int i = blockIdx.x * blockDim.x + threadIdx.x;
    if (i < N_NODES) { g_deg[i] = 0; g_cursor[i] = 0; }
}
__global__ void hist_kernel(const void* ei) {
    int e = blockIdx.x * blockDim.x + threadIdx.x;
    if (e >= N_EDGES) return;
    atomicAdd(&g_deg[load_idx(ei, (long long)N_EDGES + e)], 1);
}
__global__ void scan_blocks() {
    __shared__ int wsum[32];
    int tid = threadIdx.x, lane = tid & 31, wid = tid >> 5;
    int i = blockIdx.x * 1024 + tid;
    int v = (i < N_NODES) ? g_deg[i] : 0;
    int x = v;
#pragma unroll
    for (int off = 1; off < 32; off <<= 1) {
        int t = __shfl_up_sync(0xffffffffu, x, off);
        if (lane >= off) x += t;
    }
    if (lane == 31) wsum[wid] = x;
    __syncthreads();
    if (wid == 0) {
        int s = wsum[lane];
#pragma unroll
        for (int off = 1; off < 32; off <<= 1) {
            int t = __shfl_up_sync(0xffffffffu, s, off);
            if (lane >= off) s += t;
        }
        wsum[lane] = s;
    }
    __syncthreads();
    int excl = x - v + ((wid > 0) ? wsum[wid - 1] : 0);
    if (i < N_NODES) g_rowptr[i] = excl;
    if (tid == 0) g_bsum[blockIdx.x] = wsum[31];
}
__global__ void scan_bsums() {
    __shared__ int s2[2];
    int tid = threadIdx.x, lane = tid & 31, wid = tid >> 5;
    int v = (tid < SCAN_NB) ? g_bsum[tid] : 0;
    int x = v;
#pragma unroll
    for (int off = 1; off < 32; off <<= 1) {
        int t = __shfl_up_sync(0xffffffffu, x, off);
        if (lane >= off) x += t;
    }
    if (lane == 31) s2[wid] = x;
    __syncthreads();
    int excl = x - v + ((wid > 0) ? s2[0] : 0);
    if (tid < SCAN_NB) g_boff[tid] = excl;
    if (tid == 0) g_rowptr[N_NODES] = N_EDGES;
}
__global__ void scan_add() {
    int i = blockIdx.x * 1024 + threadIdx.x;
    if (blockIdx.x > 0 && i < N_NODES) g_rowptr[i] += g_boff[blockIdx.x];
}
__global__ void fill_kernel(const void* ei, const float* __restrict__ ew) {
    int e = blockIdx.x * blockDim.x + threadIdx.x;
    if (e >= N_EDGES) return;
    int src = load_idx(ei, e);
    int dst = load_idx(ei, (long long)N_EDGES + e);
    int p = g_rowptr[dst] + atomicAdd(&g_cursor[dst], 1);
    g_csr_src[p] = src;
    g_csr_w[p]   = ew[e];
}

// ---------------- fp32 -> bf16 hi/lo split of emb ----------------
__global__ void conv_hilo(const float* __restrict__ x) {
    int i = blockIdx.x * blockDim.x + threadIdx.x;      // over N_NODES*HID/4
    if (i >= N_NODES * HID / 4) return;
    float4 v = ((const float4*)x)[i];
    float f[4] = {v.x, v.y, v.z, v.w};
    __align__(8) __nv_bfloat16 h[4], l[4];
#pragma unroll
    for (int j = 0; j < 4; j++) {
        h[j] = __float2bfloat16_rn(f[j]);
        l[j] = __float2bfloat16_rn(f[j] - __bfloat162float(h[j]));
    }
    ((uint2*)g_A1hi)[i] = *(uint2*)h;
    ((uint2*)g_A1lo)[i] = *(uint2*)l;
}

// ---------------- weight transpose + split: Wt[n][k] = W[k][n] ----------------
template <int LAYER>
__global__ void conv_wt(const float* __restrict__ Wa, const float* __restrict__ Wb) {
    constexpr int NTOT = (LAYER == 1) ? 512 : 256;
    constexpr int NH   = (LAYER == 1) ? 256 : 128;
    __nv_bfloat16* thi = (LAYER == 1) ? g_Wt1hi : g_Wt2hi;
    __nv_bfloat16* tlo = (LAYER == 1) ? g_Wt1lo : g_Wt2lo;
    int idx = blockIdx.x * blockDim.x + threadIdx.x;    // over NTOT*256
    if (idx >= NTOT * 256) return;
    int n = idx >> 8, k = idx & 255;
    float v = (n < NH) ? Wa[(size_t)k * NH + n] : Wb[(size_t)k * NH + (n - NH)];
    __nv_bfloat16 h = __float2bfloat16_rn(v);
    thi[idx] = h;
    tlo[idx] = __float2bfloat16_rn(v - __bfloat162float(h));
}

// ---------------- mma.sync bf16 split GEMM ----------------
// D[row0:+128][bn0:+128] = A[.,256] @ Wt[bn0:+128, 256]^T  via hi*hi+hi*lo+lo*hi
// CTA 128x128, 8 warps (warp tile 64x32), K-chunks of 32, cp.async double buffer.
#define GBUF 32768
#define GSM_TOTAL (2 * GBUF)

template <int LAYER>
__global__ void __launch_bounds__(256, 1) gemm_mma() {
    const __nv_bfloat16* __restrict__ Ahi = (LAYER == 1) ? g_A1hi : g_h1hi;
    const __nv_bfloat16* __restrict__ Alo = (LAYER == 1) ? g_A1lo : g_h1lo;
    const __nv_bfloat16* __restrict__ Bhi = (LAYER == 1) ? g_Wt1hi : g_Wt2hi;
    const __nv_bfloat16* __restrict__ Blo = (LAYER == 1) ? g_Wt1lo : g_Wt2lo;

    const int bn0 = blockIdx.y * 128;
    float* __restrict__ out;
    int ostride, ocol0;
    if (LAYER == 1) {
        out = (bn0 < 256) ? g_T1l : g_T1r;
        ostride = 256; ocol0 = bn0 & 255;
    } else {
        out = (bn0 == 0) ? g_T2l : g_T2r;
        ostride = 128; ocol0 = 0;
    }

    extern __shared__ char smem[];
    uint32_t sb = smem_u32(smem);
    int tid = threadIdx.x, wid = tid >> 5, lane = tid & 31;
    int wm = (wid & 1) * 64, wn = (wid >> 1) * 32;
    int row0 = blockIdx.x * 128;

    float acc[4][4][4];
#pragma unroll
    for (int a = 0; a < 4; a++)
#pragma unroll
        for (int b = 0; b < 4; b++)
#pragma unroll
            for (int c = 0; c < 4; c++) acc[a][b][c] = 0.f;

    auto issue = [&](int kc) {
        uint32_t bb = sb + (uint32_t)(kc & 1) * GBUF;
#pragma unroll
        for (int i = 0; i < 2; i++) {
            int u = tid + i * 256;          // 0..511
            int r = u >> 2, c4 = u & 3;
            uint32_t d = SW128((uint32_t)(r * 64 + c4 * 16));
            size_t goA = (size_t)(row0 + r) * 256 + kc * 32 + c4 * 8;
            size_t goB = (size_t)(bn0 + r) * 256 + kc * 32 + c4 * 8;
            cpa16(bb + d,          Ahi + goA);
            cpa16(bb + 8192 + d,   Alo + goA);
            cpa16(bb + 16384 + d,  Bhi + goB);
            cpa16(bb + 24576 + d,  Blo + goB);
        }
        CP_COMMIT();
    };

    int lrow8 = ((lane >> 3) & 1) * 8 + (lane & 7);
    int lkoff = (lane >> 4);

    issue(0);
    for (int kc = 0; kc < 8; kc++) {
        if (kc + 1 < 8) { issue(kc + 1); CP_WAIT(1); } else { CP_WAIT(0); }
        __syncthreads();
        uint32_t bb = sb + (uint32_t)(kc & 1) * GBUF;
        uint32_t aH = bb, aL = bb + 8192, bH = bb + 16384, bL = bb + 24576;
#pragma unroll
        for (int k16 = 0; k16 < 2; k16++) {
            uint32_t ah[4][4], al[4][4], bh[2][4], bl[2][4];
#pragma unroll
            for (int fm = 0; fm < 4; fm++) {
                int row = wm + fm * 16 + lrow8;
                uint32_t ad = SW128((uint32_t)(row * 64 + (k16 * 2 + lkoff) * 16));
                ldmx4(ah[fm], aH + ad);
                ldmx4(al[fm], aL + ad);
            }
#pragma unroll
            for (int g = 0; g < 2; g++) {
                int row = wn + g * 16 + lrow8;
                uint32_t bd = SW128((uint32_t)(row * 64 + (k16 * 2 + lkoff) * 16));
                ldmx4(bh[g], bH + bd);
                ldmx4(bl[g], bL + bd);
            }
#pragma unroll
            for (int fm = 0; fm < 4; fm++)
#pragma unroll
                for (int fn = 0; fn < 4; fn++) {
                    int g = fn >> 1, p = fn & 1;
                    mma16816(acc[fm][fn], ah[fm], bh[g][p], bh[g][p + 2]);  // hi*hi
                    mma16816(acc[fm][fn], ah[fm], bl[g][p], bl[g][p + 2]);  // hi*lo
                    mma16816(acc[fm][fn], al[fm], bh[g][p], bh[g][p + 2]);  // lo*hi
                }
        }
        __syncthreads();
    }

#pragma unroll
    for (int fm = 0; fm < 4; fm++) {
        int r = row0 + wm + fm * 16 + (lane >> 2);
#pragma unroll
        for (int fn = 0; fn < 4; fn++) {
            int c = ocol0 + wn + fn * 8 + (lane & 3) * 2;
            if (r < N_NODES)
                *(float2*)(out + (size_t)r * ostride + c) =
                    make_float2(acc[fm][fn][0], acc[fm][fn][1]);
            if (r + 8 < N_NODES)
                *(float2*)(out + (size_t)(r + 8) * ostride + c) =
                    make_float2(acc[fm][fn][2], acc[fm][fn][3]);
        }
    }
}

// ---------------- AGG1: h1 = relu(meanagg(T1l) + T1r + b1) -> bf16 hi/lo ----------------
__device__ __forceinline__ void split_store4(__nv_bfloat16* hi, __nv_bfloat16* lo, float4 v) {
    float f[4] = {v.x, v.y, v.z, v.w};
    __align__(8) __nv_bfloat16 h[4], l[4];
#pragma unroll
    for (int i = 0; i < 4; i++) {
        h[i] = __float2bfloat16_rn(f[i]);
        l[i] = __float2bfloat16_rn(f[i] - __bfloat162float(h[i]));
    }
    *(uint2*)hi = *(uint2*)h;
    *(uint2*)lo = *(uint2*)l;
}

__global__ void agg1_kernel(const float* __restrict__ b1) {
    int gw = (blockIdx.x * blockDim.x + threadIdx.x) >> 5;
    int lane = threadIdx.x & 31;
    if (gw >= N_NODES) return;
    int beg = g_rowptr[gw], end = g_rowptr[gw + 1];
    float4 a0 = make_float4(0.f, 0.f, 0.f, 0.f);
    float4 a1 = make_float4(0.f, 0.f, 0.f, 0.f);
    int i = beg;
    for (; i + 1 < end; i += 2) {
        int   s0 = g_csr_src[i], s1 = g_csr_src[i + 1];
        float w0 = g_csr_w[i],   w1 = g_csr_w[i + 1];
        const float4* r0 = (const float4*)(g_T1l + (size_t)s0 * HID);
        const float4* r1 = (const float4*)(g_T1l + (size_t)s1 * HID);
        float4 u0 = r0[lane], u1 = r0[lane + 32];
        float4 v0 = r1[lane], v1 = r1[lane + 32];
        a0.x += u0.x * w0; a0.y += u0.y * w0; a0.z += u0.z * w0; a0.w += u0.w * w0;
        a1.x += u1.x * w0; a1.y += u1.y * w0; a1.z += u1.z * w0; a1.w += u1.w * w0;
        a0.x += v0.x * w1; a0.y += v0.y * w1; a0.z += v0.z * w1; a0.w += v0.w * w1;
        a1.x += v1.x * w1; a1.y += v1.y * w1; a1.z += v1.z * w1; a1.w += v1.w * w1;
    }
    if (i < end) {
        int   s = g_csr_src[i];
        float w = g_csr_w[i];
        const float4* r = (const float4*)(g_T1l + (size_t)s * HID);
        float4 u0 = r[lane], u1 = r[lane + 32];
        a0.x += u0.x * w; a0.y += u0.y * w; a0.z += u0.z * w; a0.w += u0.w * w;
        a1.x += u1.x * w; a1.y += u1.y * w; a1.z += u1.z * w; a1.w += u1.w * w;
    }
    float inv = 1.0f / fmaxf((float)(end - beg), 1.0f);
    const float4* tr = (const float4*)(g_T1r + (size_t)gw * HID);
    float4 t0 = tr[lane], t1 = tr[lane + 32];
    const float4* bb = (const float4*)b1;
    float4 c0 = bb[lane], c1 = bb[lane + 32];
    float4 o0, o1;
    o0.x = fmaxf(a0.x * inv + t0.x + c0.x, 0.f);
    o0.y = fmaxf(a0.y * inv + t0.y + c0.y, 0.f);
    o0.z = fmaxf(a0.z * inv + t0.z + c0.z, 0.f);
    o0.w = fmaxf(a0.w * inv + t0.w + c0.w, 0.f);
    o1.x = fmaxf(a1.x * inv + t1.x + c1.x, 0.f);
    o1.y = fmaxf(a1.y * inv + t1.y + c1.y, 0.f);
    o1.z = fmaxf(a1.z * inv + t1.z + c1.z, 0.f);
    o1.w = fmaxf(a1.w * inv + t1.w + c1.w, 0.f);
    split_store4(g_h1hi + (size_t)gw * HID + lane * 4,
                 g_h1lo + (size_t)gw * HID + lane * 4, o0);
    split_store4(g_h1hi + (size_t)gw * HID + 128 + lane * 4,
                 g_h1lo + (size_t)gw * HID + 128 + lane * 4, o1);
}

// ---------------- AGG2: out = meanagg(T2l) + T2r + b2 ----------------
__global__ void agg2_kernel(const float* __restrict__ b2, float* __restrict__ out) {
    int gw = (blockIdx.x * blockDim.x + threadIdx.x) >> 5;
    int lane = threadIdx.x & 31;
    if (gw >= N_NODES) return;
    int beg = g_rowptr[gw], end = g_rowptr[gw + 1];
    float4 a = make_float4(0.f, 0.f, 0.f, 0.f);
    int i = beg;
    for (; i + 3 < end; i += 4) {
        int s0 = g_csr_src[i], s1 = g_csr_src[i + 1], s2 = g_csr_src[i + 2], s3 = g_csr_src[i + 3];
        float w0 = g_csr_w[i], w1 = g_csr_w[i + 1], w2 = g_csr_w[i + 2], w3 = g_csr_w[i + 3];
        float4 u0 = ((const float4*)(g_T2l + (size_t)s0 * EMB))[lane];
        float4 u1 = ((const float4*)(g_T2l + (size_t)s1 * EMB))[lane];
        float4 u2 = ((const float4*)(g_T2l + (size_t)s2 * EMB))[lane];
        float4 u3 = ((const float4*)(g_T2l + (size_t)s3 * EMB))[lane];
        a.x += u0.x * w0 + u1.x * w1 + u2.x * w2 + u3.x * w3;
        a.y += u0.y * w0 + u1.y * w1 + u2.y * w2 + u3.y * w3;
        a.z += u0.z * w0 + u1.z * w1 + u2.z * w2 + u3.z * w3;
        a.w += u0.w * w0 + u1.w * w1 + u2.w * w2 + u3.w * w3;
    }
    for (; i < end; i++) {
        int s = g_csr_src[i];
        float w = g_csr_w[i];
        float4 u = ((const float4*)(g_T2l + (size_t)s * EMB))[lane];
        a.x += u.x * w; a.y += u.y * w; a.z += u.z * w; a.w += u.w * w;
    }
    float inv = 1.0f / fmaxf((float)(end - beg), 1.0f);
    float4 t = ((const float4*)(g_T2r + (size_t)gw * EMB))[lane];
    float4 c = ((const float4*)b2)[lane];
    float4 o;
    o.x = a.x * inv + t.x + c.x;
    o.y = a.y * inv + t.y + c.y;
    o.z = a.z * inv + t.z + c.z;
    o.w = a.w * inv + t.w + c.w;
    ((float4*)(out + (size_t)gw * EMB))[lane] = o;
}

// ---------------- streams/events for intra-graph concurrency ----------------
// Created at static-init time (before the harness's memory checkpoints).
struct ForkCtx {
    cudaStream_t side = nullptr;
    cudaEvent_t  ev0 = nullptr, ev1 = nullptr;
    bool ok = false;
    ForkCtx() {
        if (cudaStreamCreateWithFlags(&side, cudaStreamNonBlocking) == cudaSuccess &&
            cudaEventCreateWithFlags(&ev0, cudaEventDisableTiming) == cudaSuccess &&
            cudaEventCreateWithFlags(&ev1, cudaEventDisableTiming) == cudaSuccess)
            ok = true;
    }
};
static ForkCtx g_fork;

// ---------------- launch ----------------
extern "C" void kernel_launch(void* const* d_in, const int* in_sizes, int n_in,
                              void* d_out, int out_size) {
    const void*  ei  = d_in[1];
    const float* ew  = (const float*)d_in[2];
    const float* emb = (const float*)d_in[3];
    const float* W1l = (const float*)d_in[4];
    const float* W1r = (const float*)d_in[5];
    const float* b1  = (const float*)d_in[6];
    const float* W2l = (const float*)d_in[7];
    const float* W2r = (const float*)d_in[8];
    const float* b2  = (const float*)d_in[9];
    float* out = (float*)d_out;

    static bool attr_done = false;
    if (!attr_done) {
        cudaFuncSetAttribute(gemm_mma<1>, cudaFuncAttributeMaxDynamicSharedMemorySize, GSM_TOTAL);
        cudaFuncSetAttribute(gemm_mma<2>, cudaFuncAttributeMaxDynamicSharedMemorySize, GSM_TOTAL);
        attr_done = true;
    }

    if (g_fork.ok) {
        cudaStream_t S = g_fork.side;
        // fork: root the side stream in the captured graph
        cudaEventRecord(g_fork.ev0, 0);
        cudaStreamWaitEvent(S, g_fork.ev0, 0);

        // main stream: conversions + layer-1 GEMM (independent of CSR)
        conv_hilo<<<(N_NODES * HID / 4 + 255) / 256, 256>>>(emb);
        conv_wt<1><<<(512 * 256 + 255) / 256, 256>>>(W1l, W1r);
        conv_wt<2><<<(256 * 256 + 255) / 256, 256>>>(W2l, W2r);
        { dim3 g(M_TILES, 4); gemm_mma<1><<<g, 256, GSM_TOTAL>>>(); }

        // side stream: CSR build
        probe_kernel<<<1, 256, 0, S>>>(ei);
        zero_kernel<<<(N_NODES + 255) / 256, 256, 0, S>>>();
        hist_kernel<<<(N_EDGES + 255) / 256, 256, 0, S>>>(ei);
        scan_blocks<<<SCAN_NB, 1024, 0, S>>>();
        scan_bsums<<<1, 64, 0, S>>>();
        scan_add<<<SCAN_NB, 1024, 0, S>>>();
        fill_kernel<<<(N_EDGES + 255) / 256, 256, 0, S>>>(ei, ew);

        // join: agg1 needs CSR + gemm1
        cudaEventRecord(g_fork.ev1, S);
        cudaStreamWaitEvent(0, g_fork.ev1, 0);

        agg1_kernel<<<(N_NODES * 32 + 255) / 256, 256>>>(b1);
        { dim3 g(M_TILES, 2); gemm_mma<2><<<g, 256, GSM_TOTAL>>>(); }
        agg2_kernel<<<(N_NODES * 32 + 255) / 256, 256>>>(b2, out);
    } else {
        // serial fallback (identical to R6)
        probe_kernel<<<1, 256>>>(ei);
        zero_kernel<<<(N_NODES + 255) / 256, 256>>>();
        hist_kernel<<<(N_EDGES + 255) / 256, 256>>>(ei);
        scan_blocks<<<SCAN_NB, 1024>>>();
        scan_bsums<<<1, 64>>>();
        scan_add<<<SCAN_NB, 1024>>>();
        fill_kernel<<<(N_EDGES + 255) / 256, 256>>>(ei, ew);
        conv_hilo<<<(N_NODES * HID / 4 + 255) / 256, 256>>>(emb);
        conv_wt<1><<<(512 * 256 + 255) / 256, 256>>>(W1l, W1r);
        conv_wt<2><<<(256 * 256 + 255) / 256, 256>>>(W2l, W2r);
        { dim3 g(M_TILES, 4); gemm_mma<1><<<g, 256, GSM_TOTAL>>>(); }
        agg1_kernel<<<(N_NODES * 32 + 255) / 256, 256>>>(b1);
        { dim3 g(M_TILES, 2); gemm_mma<2><<<g, 256, GSM_TOTAL>>>(); }
        agg2_kernel<<<(N_NODES * 32 + 255) / 256, 256>>>(b2, out);
    }
}

// round 10
// speedup vs baseline: 2.5498x; 1.1192x over previous
#include <cuda_runtime.h>
#include <cuda_bf16.h>
#include <cstdint>

#define N_NODES 50000
#define N_EDGES 800000
#define HID 256
#define EMB 128
#define M_TILES 391                 // ceil(50000/128)
#define M_PAD (M_TILES * 128)       // 50048
#define SCAN_NB ((N_NODES + 1023) / 1024)   // 49

// ---------------- scratch (device globals; no runtime allocation) ----------------
__device__ int   g_is64;
__device__ int   g_deg[N_NODES];
__device__ int   g_rowptr[N_NODES + 1];
__device__ int   g_cursor[N_NODES];
__device__ int   g_bsum[SCAN_NB];
__device__ int   g_boff[SCAN_NB];
__device__ int   g_csr_src[N_EDGES];
__device__ float g_csr_w[N_EDGES];

// bf16 hi/lo split inputs (padded to M_PAD rows; pad stays zero from BSS init)
__device__ __nv_bfloat16 g_A1hi[(size_t)M_PAD * HID];
__device__ __nv_bfloat16 g_A1lo[(size_t)M_PAD * HID];
__device__ __nv_bfloat16 g_h1hi[(size_t)M_PAD * HID];
__device__ __nv_bfloat16 g_h1lo[(size_t)M_PAD * HID];
// transposed weights [N,K] bf16 hi/lo
__device__ __nv_bfloat16 g_Wt1hi[512 * 256];
__device__ __nv_bfloat16 g_Wt1lo[512 * 256];
__device__ __nv_bfloat16 g_Wt2hi[256 * 256];
__device__ __nv_bfloat16 g_Wt2lo[256 * 256];
// GEMM outputs
__device__ float g_T1l[(size_t)N_NODES * HID];
__device__ float g_T1r[(size_t)N_NODES * HID];
__device__ float g_T2l[(size_t)N_NODES * EMB];
__device__ float g_T2r[(size_t)N_NODES * EMB];

// ---------------- PTX helpers (sm_80-era only: cp.async, ldmatrix, mma.sync) ----------------
__device__ __forceinline__ uint32_t smem_u32(const void* p) {
    uint32_t r;
    asm("{ .reg .u64 t; cvta.to.shared.u64 t, %1; cvt.u32.u64 %0, t; }" : "=r"(r) : "l"(p));
    return r;
}
__device__ __forceinline__ void cpa16(uint32_t dst, const void* src) {
    asm volatile("cp.async.cg.shared.global [%0], [%1], 16;" :: "r"(dst), "l"(src));
}
#define CP_COMMIT() asm volatile("cp.async.commit_group;" ::: "memory")
#define CP_WAIT(n)  asm volatile("cp.async.wait_group %0;" :: "n"(n) : "memory")

__device__ __forceinline__ void ldmx4(uint32_t* d, uint32_t addr) {
    asm volatile("ldmatrix.sync.aligned.m8n8.x4.shared.b16 {%0,%1,%2,%3}, [%4];"
                 : "=r"(d[0]), "=r"(d[1]), "=r"(d[2]), "=r"(d[3]) : "r"(addr));
}
__device__ __forceinline__ void mma16816(float* C, const uint32_t* A, uint32_t b0, uint32_t b1) {
    asm volatile(
        "mma.sync.aligned.m16n8k16.row.col.f32.bf16.bf16.f32 "
        "{%0,%1,%2,%3}, {%4,%5,%6,%7}, {%8,%9}, {%0,%1,%2,%3};"
        : "+f"(C[0]), "+f"(C[1]), "+f"(C[2]), "+f"(C[3])
        : "r"(A[0]), "r"(A[1]), "r"(A[2]), "r"(A[3]), "r"(b0), "r"(b1));
}
#define SW128(x) ((x) ^ (((x) >> 3) & 0x70))

// ---------------- edge-index dtype probe ----------------
__global__ void probe_kernel(const void* ei) {
    __shared__ int ok;
    if (threadIdx.x == 0) ok = 1;
    __syncthreads();
    long long v = ((const long long*)ei)[threadIdx.x];
    if (v < 0 || v >= (long long)N_NODES) atomicExch(&ok, 0);
    __syncthreads();
    if (threadIdx.x == 0) g_is64 = ok;
}
__device__ __forceinline__ int load_idx(const void* ei, long long pos) {
    return g_is64 ? (int)((const long long*)ei)[pos] : ((const int*)ei)[pos];
}

// ---------------- CSR build ----------------
__global__ void zero_kernel() {
    int i = blockIdx.x * blockDim.x + threadIdx.x;
    if (i < N_NODES) { g_deg[i] = 0; g_cursor[i] = 0; }
}
__global__ void hist_kernel(const void* ei) {
    int e = blockIdx.x * blockDim.x + threadIdx.x;
    if (e >= N_EDGES) return;
    atomicAdd(&g_deg[load_idx(ei, (long long)N_EDGES + e)], 1);
}
__global__ void scan_blocks() {
    __shared__ int wsum[32];
    int tid = threadIdx.x, lane = tid & 31, wid = tid >> 5;
    int i = blockIdx.x * 1024 + tid;
    int v = (i < N_NODES) ? g_deg[i] : 0;
    int x = v;
#pragma unroll
    for (int off = 1; off < 32; off <<= 1) {
        int t = __shfl_up_sync(0xffffffffu, x, off);
        if (lane >= off) x += t;
    }
    if (lane == 31) wsum[wid] = x;
    __syncthreads();
    if (wid == 0) {
        int s = wsum[lane];
#pragma unroll
        for (int off = 1; off < 32; off <<= 1) {
            int t = __shfl_up_sync(0xffffffffu, s, off);
            if (lane >= off) s += t;
        }
        wsum[lane] = s;
    }
    __syncthreads();
    int excl = x - v + ((wid > 0) ? wsum[wid - 1] : 0);
    if (i < N_NODES) g_rowptr[i] = excl;
    if (tid == 0) g_bsum[blockIdx.x] = wsum[31];
}
__global__ void scan_bsums() {
    __shared__ int s2[2];
    int tid = threadIdx.x, lane = tid & 31, wid = tid >> 5;
    int v = (tid < SCAN_NB) ? g_bsum[tid] : 0;
    int x = v;
#pragma unroll
    for (int off = 1; off < 32; off <<= 1) {
        int t = __shfl_up_sync(0xffffffffu, x, off);
        if (lane >= off) x += t;
    }
    if (lane == 31) s2[wid] = x;
    __syncthreads();
    int excl = x - v + ((wid > 0) ? s2[0] : 0);
    if (tid < SCAN_NB) g_boff[tid] = excl;
    if (tid == 0) g_rowptr[N_NODES] = N_EDGES;
}
__global__ void scan_add() {
    int i = blockIdx.x * 1024 + threadIdx.x;
    if (blockIdx.x > 0 && i < N_NODES) g_rowptr[i] += g_boff[blockIdx.x];
}
__global__ void fill_kernel(const void* ei, const float* __restrict__ ew) {
    int e = blockIdx.x * blockDim.x + threadIdx.x;
    if (e >= N_EDGES) return;
    int src = load_idx(ei, e);
    int dst = load_idx(ei, (long long)N_EDGES + e);
    int p = g_rowptr[dst] + atomicAdd(&g_cursor[dst], 1);
    g_csr_src[p] = src;
    g_csr_w[p]   = ew[e];
}

// ---------------- fp32 -> bf16 hi/lo split of emb ----------------
__global__ void conv_hilo(const float* __restrict__ x) {
    int i = blockIdx.x * blockDim.x + threadIdx.x;      // over N_NODES*HID/4
    if (i >= N_NODES * HID / 4) return;
    float4 v = ((const float4*)x)[i];
    float f[4] = {v.x, v.y, v.z, v.w};
    __align__(8) __nv_bfloat16 h[4], l[4];
#pragma unroll
    for (int j = 0; j < 4; j++) {
        h[j] = __float2bfloat16_rn(f[j]);
        l[j] = __float2bfloat16_rn(f[j] - __bfloat162float(h[j]));
    }
    ((uint2*)g_A1hi)[i] = *(uint2*)h;
    ((uint2*)g_A1lo)[i] = *(uint2*)l;
}

// ---------------- weight transpose + split: Wt[n][k] = W[k][n] ----------------
template <int LAYER>
__global__ void conv_wt(const float* __restrict__ Wa, const float* __restrict__ Wb) {
    constexpr int NTOT = (LAYER == 1) ? 512 : 256;
    constexpr int NH   = (LAYER == 1) ? 256 : 128;
    __nv_bfloat16* thi = (LAYER == 1) ? g_Wt1hi : g_Wt2hi;
    __nv_bfloat16* tlo = (LAYER == 1) ? g_Wt1lo : g_Wt2lo;
    int idx = blockIdx.x * blockDim.x + threadIdx.x;    // over NTOT*256
    if (idx >= NTOT * 256) return;
    int n = idx >> 8, k = idx & 255;
    float v = (n < NH) ? Wa[(size_t)k * NH + n] : Wb[(size_t)k * NH + (n - NH)];
    __nv_bfloat16 h = __float2bfloat16_rn(v);
    thi[idx] = h;
    tlo[idx] = __float2bfloat16_rn(v - __bfloat162float(h));
}

// ---------------- mma.sync bf16 split GEMM ----------------
// D[row0:+128][bn0:+128] = A[.,256] @ Wt[bn0:+128, 256]^T  via hi*hi+hi*lo+lo*hi
// CTA 128x128, 8 warps (warp tile 64x32), K-chunks of 32, cp.async double buffer.
// __launch_bounds__(256,2): 2 CTAs/SM for latency hiding; inner loop ordered to
// keep peak live registers ~100 (B frags resident, A frags streamed per-fm).
#define GBUF 32768
#define GSM_TOTAL (2 * GBUF)

template <int LAYER>
__global__ void __launch_bounds__(256, 2) gemm_mma() {
    const __nv_bfloat16* __restrict__ Ahi = (LAYER == 1) ? g_A1hi : g_h1hi;
    const __nv_bfloat16* __restrict__ Alo = (LAYER == 1) ? g_A1lo : g_h1lo;
    const __nv_bfloat16* __restrict__ Bhi = (LAYER == 1) ? g_Wt1hi : g_Wt2hi;
    const __nv_bfloat16* __restrict__ Blo = (LAYER == 1) ? g_Wt1lo : g_Wt2lo;

    const int bn0 = blockIdx.y * 128;
    float* __restrict__ out;
    int ostride, ocol0;
    if (LAYER == 1) {
        out = (bn0 < 256) ? g_T1l : g_T1r;
        ostride = 256; ocol0 = bn0 & 255;
    } else {
        out = (bn0 == 0) ? g_T2l : g_T2r;
        ostride = 128; ocol0 = 0;
    }

    extern __shared__ char smem[];
    uint32_t sb = smem_u32(smem);
    int tid = threadIdx.x, wid = tid >> 5, lane = tid & 31;
    int wm = (wid & 1) * 64, wn = (wid >> 1) * 32;
    int row0 = blockIdx.x * 128;

    float acc[4][4][4];
#pragma unroll
    for (int a = 0; a < 4; a++)
#pragma unroll
        for (int b = 0; b < 4; b++)
#pragma unroll
            for (int c = 0; c < 4; c++) acc[a][b][c] = 0.f;

    auto issue = [&](int kc) {
        uint32_t bb = sb + (uint32_t)(kc & 1) * GBUF;
#pragma unroll
        for (int i = 0; i < 2; i++) {
            int u = tid + i * 256;          // 0..511
            int r = u >> 2, c4 = u & 3;
            uint32_t d = SW128((uint32_t)(r * 64 + c4 * 16));
            size_t goA = (size_t)(row0 + r) * 256 + kc * 32 + c4 * 8;
            size_t goB = (size_t)(bn0 + r) * 256 + kc * 32 + c4 * 8;
            cpa16(bb + d,          Ahi + goA);
            cpa16(bb + 8192 + d,   Alo + goA);
            cpa16(bb + 16384 + d,  Bhi + goB);
            cpa16(bb + 24576 + d,  Blo + goB);
        }
        CP_COMMIT();
    };

    int lrow8 = ((lane >> 3) & 1) * 8 + (lane & 7);
    int lkoff = (lane >> 4);

    issue(0);
    for (int kc = 0; kc < 8; kc++) {
        if (kc + 1 < 8) { issue(kc + 1); CP_WAIT(1); } else { CP_WAIT(0); }
        __syncthreads();
        uint32_t bb = sb + (uint32_t)(kc & 1) * GBUF;
        uint32_t aH = bb, aL = bb + 8192, bH = bb + 16384, bL = bb + 24576;
#pragma unroll
        for (int k16 = 0; k16 < 2; k16++) {
            // B fragments resident for the whole k16 step
            uint32_t bh[2][4], bl[2][4];
#pragma unroll
            for (int g = 0; g < 2; g++) {
                int row = wn + g * 16 + lrow8;
                uint32_t bd = SW128((uint32_t)(row * 64 + (k16 * 2 + lkoff) * 16));
                ldmx4(bh[g], bH + bd);
                ldmx4(bl[g], bL + bd);
            }
            // stream A fragments per fm to bound live registers
#pragma unroll
            for (int fm = 0; fm < 4; fm++) {
                uint32_t ah[4], al[4];
                int row = wm + fm * 16 + lrow8;
                uint32_t ad = SW128((uint32_t)(row * 64 + (k16 * 2 + lkoff) * 16));
                ldmx4(ah, aH + ad);
                ldmx4(al, aL + ad);
#pragma unroll
                for (int fn = 0; fn < 4; fn++) {
                    int g = fn >> 1, p = fn & 1;
                    mma16816(acc[fm][fn], ah, bh[g][p], bh[g][p + 2]);  // hi*hi
                    mma16816(acc[fm][fn], ah, bl[g][p], bl[g][p + 2]);  // hi*lo
                    mma16816(acc[fm][fn], al, bh[g][p], bh[g][p + 2]);  // lo*hi
                }
            }
        }
        __syncthreads();
    }

#pragma unroll
    for (int fm = 0; fm < 4; fm++) {
        int r = row0 + wm + fm * 16 + (lane >> 2);
#pragma unroll
        for (int fn = 0; fn < 4; fn++) {
            int c = ocol0 + wn + fn * 8 + (lane & 3) * 2;
            if (r < N_NODES)
                *(float2*)(out + (size_t)r * ostride + c) =
                    make_float2(acc[fm][fn][0], acc[fm][fn][1]);
            if (r + 8 < N_NODES)
                *(float2*)(out + (size_t)(r + 8) * ostride + c) =
                    make_float2(acc[fm][fn][2], acc[fm][fn][3]);
        }
    }
}

// ---------------- AGG1: h1 = relu(meanagg(T1l) + T1r + b1) -> bf16 hi/lo ----------------
__device__ __forceinline__ void split_store4(__nv_bfloat16* hi, __nv_bfloat16* lo, float4 v) {
    float f[4] = {v.x, v.y, v.z, v.w};
    __align__(8) __nv_bfloat16 h[4], l[4];
#pragma unroll
    for (int i = 0; i < 4; i++) {
        h[i] = __float2bfloat16_rn(f[i]);
        l[i] = __float2bfloat16_rn(f[i] - __bfloat162float(h[i]));
    }
    *(uint2*)hi = *(uint2*)h;
    *(uint2*)lo = *(uint2*)l;
}

__global__ void agg1_kernel(const float* __restrict__ b1) {
    int gw = (blockIdx.x * blockDim.x + threadIdx.x) >> 5;
    int lane = threadIdx.x & 31;
    if (gw >= N_NODES) return;
    int beg = g_rowptr[gw], end = g_rowptr[gw + 1];
    float4 a0 = make_float4(0.f, 0.f, 0.f, 0.f);
    float4 a1 = make_float4(0.f, 0.f, 0.f, 0.f);
    int i = beg;
    for (; i + 1 < end; i += 2) {
        int   s0 = g_csr_src[i], s1 = g_csr_src[i + 1];
        float w0 = g_csr_w[i],   w1 = g_csr_w[i + 1];
        const float4* r0 = (const float4*)(g_T1l + (size_t)s0 * HID);
        const float4* r1 = (const float4*)(g_T1l + (size_t)s1 * HID);
        float4 u0 = r0[lane], u1 = r0[lane + 32];
        float4 v0 = r1[lane], v1 = r1[lane + 32];
        a0.x += u0.x * w0; a0.y += u0.y * w0; a0.z += u0.z * w0; a0.w += u0.w * w0;
        a1.x += u1.x * w0; a1.y += u1.y * w0; a1.z += u1.z * w0; a1.w += u1.w * w0;
        a0.x += v0.x * w1; a0.y += v0.y * w1; a0.z += v0.z * w1; a0.w += v0.w * w1;
        a1.x += v1.x * w1; a1.y += v1.y * w1; a1.z += v1.z * w1; a1.w += v1.w * w1;
    }
    if (i < end) {
        int   s = g_csr_src[i];
        float w = g_csr_w[i];
        const float4* r = (const float4*)(g_T1l + (size_t)s * HID);
        float4 u0 = r[lane], u1 = r[lane + 32];
        a0.x += u0.x * w; a0.y += u0.y * w; a0.z += u0.z * w; a0.w += u0.w * w;
        a1.x += u1.x * w; a1.y += u1.y * w; a1.z += u1.z * w; a1.w += u1.w * w;
    }
    float inv = 1.0f / fmaxf((float)(end - beg), 1.0f);
    const float4* tr = (const float4*)(g_T1r + (size_t)gw * HID);
    float4 t0 = tr[lane], t1 = tr[lane + 32];
    const float4* bb = (const float4*)b1;
    float4 c0 = bb[lane], c1 = bb[lane + 32];
    float4 o0, o1;
    o0.x = fmaxf(a0.x * inv + t0.x + c0.x, 0.f);
    o0.y = fmaxf(a0.y * inv + t0.y + c0.y, 0.f);
    o0.z = fmaxf(a0.z * inv + t0.z + c0.z, 0.f);
    o0.w = fmaxf(a0.w * inv + t0.w + c0.w, 0.f);
    o1.x = fmaxf(a1.x * inv + t1.x + c1.x, 0.f);
    o1.y = fmaxf(a1.y * inv + t1.y + c1.y, 0.f);
    o1.z = fmaxf(a1.z * inv + t1.z + c1.z, 0.f);
    o1.w = fmaxf(a1.w * inv + t1.w + c1.w, 0.f);
    split_store4(g_h1hi + (size_t)gw * HID + lane * 4,
                 g_h1lo + (size_t)gw * HID + lane * 4, o0);
    split_store4(g_h1hi + (size_t)gw * HID + 128 + lane * 4,
                 g_h1lo + (size_t)gw * HID + 128 + lane * 4, o1);
}

// ---------------- AGG2: out = meanagg(T2l) + T2r + b2 ----------------
__global__ void agg2_kernel(const float* __restrict__ b2, float* __restrict__ out) {
    int gw = (blockIdx.x * blockDim.x + threadIdx.x) >> 5;
    int lane = threadIdx.x & 31;
    if (gw >= N_NODES) return;
    int beg = g_rowptr[gw], end = g_rowptr[gw + 1];
    float4 a = make_float4(0.f, 0.f, 0.f, 0.f);
    int i = beg;
    for (; i + 3 < end; i += 4) {
        int s0 = g_csr_src[i], s1 = g_csr_src[i + 1], s2 = g_csr_src[i + 2], s3 = g_csr_src[i + 3];
        float w0 = g_csr_w[i], w1 = g_csr_w[i + 1], w2 = g_csr_w[i + 2], w3 = g_csr_w[i + 3];
        float4 u0 = ((const float4*)(g_T2l + (size_t)s0 * EMB))[lane];
        float4 u1 = ((const float4*)(g_T2l + (size_t)s1 * EMB))[lane];
        float4 u2 = ((const float4*)(g_T2l + (size_t)s2 * EMB))[lane];
        float4 u3 = ((const float4*)(g_T2l + (size_t)s3 * EMB))[lane];
        a.x += u0.x * w0 + u1.x * w1 + u2.x * w2 + u3.x * w3;
        a.y += u0.y * w0 + u1.y * w1 + u2.y * w2 + u3.y * w3;
        a.z += u0.z * w0 + u1.z * w1 + u2.z * w2 + u3.z * w3;
        a.w += u0.w * w0 + u1.w * w1 + u2.w * w2 + u3.w * w3;
    }
    for (; i < end; i++) {
        int s = g_csr_src[i];
        float w = g_csr_w[i];
        float4 u = ((const float4*)(g_T2l + (size_t)s * EMB))[lane];
        a.x += u.x * w; a.y += u.y * w; a.z += u.z * w; a.w += u.w * w;
    }
    float inv = 1.0f / fmaxf((float)(end - beg), 1.0f);
    float4 t = ((const float4*)(g_T2r + (size_t)gw * EMB))[lane];
    float4 c = ((const float4*)b2)[lane];
    float4 o;
    o.x = a.x * inv + t.x + c.x;
    o.y = a.y * inv + t.y + c.y;
    o.z = a.z * inv + t.z + c.z;
    o.w = a.w * inv + t.w + c.w;
    ((float4*)(out + (size_t)gw * EMB))[lane] = o;
}

// ---------------- streams/events for intra-graph concurrency ----------------
struct ForkCtx {
    cudaStream_t side = nullptr;
    cudaEvent_t  ev0 = nullptr, ev1 = nullptr;
    bool ok = false;
    ForkCtx() {
        if (cudaStreamCreateWithFlags(&side, cudaStreamNonBlocking) == cudaSuccess &&
            cudaEventCreateWithFlags(&ev0, cudaEventDisableTiming) == cudaSuccess &&
            cudaEventCreateWithFlags(&ev1, cudaEventDisableTiming) == cudaSuccess)
            ok = true;
    }
};
static ForkCtx g_fork;

// ---------------- launch ----------------
extern "C" void kernel_launch(void* const* d_in, const int* in_sizes, int n_in,
                              void* d_out, int out_size) {
    const void*  ei  = d_in[1];
    const float* ew  = (const float*)d_in[2];
    const float* emb = (const float*)d_in[3];
    const float* W1l = (const float*)d_in[4];
    const float* W1r = (const float*)d_in[5];
    const float* b1  = (const float*)d_in[6];
    const float* W2l = (const float*)d_in[7];
    const float* W2r = (const float*)d_in[8];
    const float* b2  = (const float*)d_in[9];
    float* out = (float*)d_out;

    static bool attr_done = false;
    if (!attr_done) {
        cudaFuncSetAttribute(gemm_mma<1>, cudaFuncAttributeMaxDynamicSharedMemorySize, GSM_TOTAL);
        cudaFuncSetAttribute(gemm_mma<2>, cudaFuncAttributeMaxDynamicSharedMemorySize, GSM_TOTAL);
        attr_done = true;
    }

    if (g_fork.ok) {
        cudaStream_t S = g_fork.side;
        cudaEventRecord(g_fork.ev0, 0);
        cudaStreamWaitEvent(S, g_fork.ev0, 0);

        // main stream: conversions + layer-1 GEMM (independent of CSR)
        conv_hilo<<<(N_NODES * HID / 4 + 255) / 256, 256>>>(emb);
        conv_wt<1><<<(512 * 256 + 255) / 256, 256>>>(W1l, W1r);
        conv_wt<2><<<(256 * 256 + 255) / 256, 256>>>(W2l, W2r);
        { dim3 g(M_TILES, 4); gemm_mma<1><<<g, 256, GSM_TOTAL>>>(); }

        // side stream: CSR build
        probe_kernel<<<1, 256, 0, S>>>(ei);
        zero_kernel<<<(N_NODES + 255) / 256, 256, 0, S>>>();
        hist_kernel<<<(N_EDGES + 255) / 256, 256, 0, S>>>(ei);
        scan_blocks<<<SCAN_NB, 1024, 0, S>>>();
        scan_bsums<<<1, 64, 0, S>>>();
        scan_add<<<SCAN_NB, 1024, 0, S>>>();
        fill_kernel<<<(N_EDGES + 255) / 256, 256, 0, S>>>(ei, ew);

        cudaEventRecord(g_fork.ev1, S);
        cudaStreamWaitEvent(0, g_fork.ev1, 0);

        agg1_kernel<<<(N_NODES * 32 + 255) / 256, 256>>>(b1);
        { dim3 g(M_TILES, 2); gemm_mma<2><<<g, 256, GSM_TOTAL>>>(); }
        agg2_kernel<<<(N_NODES * 32 + 255) / 256, 256>>>(b2, out);
    } else {
        probe_kernel<<<1, 256>>>(ei);
        zero_kernel<<<(N_NODES + 255) / 256, 256>>>();
        hist_kernel<<<(N_EDGES + 255) / 256, 256>>>(ei);
        scan_blocks<<<SCAN_NB, 1024>>>();
        scan_bsums<<<1, 64>>>();
        scan_add<<<SCAN_NB, 1024>>>();
        fill_kernel<<<(N_EDGES + 255) / 256, 256>>>(ei, ew);
        conv_hilo<<<(N_NODES * HID / 4 + 255) / 256, 256>>>(emb);
        conv_wt<1><<<(512 * 256 + 255) / 256, 256>>>(W1l, W1r);
        conv_wt<2><<<(256 * 256 + 255) / 256, 256>>>(W2l, W2r);
        { dim3 g(M_TILES, 4); gemm_mma<1><<<g, 256, GSM_TOTAL>>>(); }
        agg1_kernel<<<(N_NODES * 32 + 255) / 256, 256>>>(b1);
        { dim3 g(M_TILES, 2); gemm_mma<2><<<g, 256, GSM_TOTAL>>>(); }
        agg2_kernel<<<(N_NODES * 32 + 255) / 256, 256>>>(b2, out);
    }
}

// round 11
// speedup vs baseline: 2.5527x; 1.0011x over previous
#include <cuda_runtime.h>
#include <cuda_bf16.h>
#include <cstdint>

#define N_NODES 50000
#define N_EDGES 800000
#define HID 256
#define EMB 128
#define M_TILES 391                 // ceil(50000/128)
#define M_PAD (M_TILES * 128)       // 50048
#define SCAN_NB ((N_NODES + 1023) / 1024)   // 49

// ---------------- scratch (device globals; no runtime allocation) ----------------
__device__ int   g_is64;
__device__ int   g_deg[N_NODES];
__device__ int   g_rowptr[N_NODES + 1];
__device__ int   g_cursor[N_NODES];
__device__ int   g_bsum[SCAN_NB];
__device__ int   g_boff[SCAN_NB];
__device__ int   g_csr_src[N_EDGES];
__device__ float g_csr_w[N_EDGES];

// bf16 hi/lo split inputs (padded to M_PAD rows; pad stays zero from BSS init)
__device__ __nv_bfloat16 g_A1hi[(size_t)M_PAD * HID];
__device__ __nv_bfloat16 g_A1lo[(size_t)M_PAD * HID];
__device__ __nv_bfloat16 g_h1hi[(size_t)M_PAD * HID];
__device__ __nv_bfloat16 g_h1lo[(size_t)M_PAD * HID];
// transposed weights [N,K] bf16 hi/lo
__device__ __nv_bfloat16 g_Wt1hi[512 * 256];
__device__ __nv_bfloat16 g_Wt1lo[512 * 256];
__device__ __nv_bfloat16 g_Wt2hi[256 * 256];
__device__ __nv_bfloat16 g_Wt2lo[256 * 256];
// GEMM outputs
__device__ float g_T1l[(size_t)N_NODES * HID];
__device__ float g_T1r[(size_t)N_NODES * HID];
__device__ float g_T2l[(size_t)N_NODES * EMB];
__device__ float g_T2r[(size_t)N_NODES * EMB];

// ---------------- PTX helpers (sm_80-era only: cp.async, ldmatrix, mma.sync) ----------------
__device__ __forceinline__ uint32_t smem_u32(const void* p) {
    uint32_t r;
    asm("{ .reg .u64 t; cvta.to.shared.u64 t, %1; cvt.u32.u64 %0, t; }" : "=r"(r) : "l"(p));
    return r;
}
__device__ __forceinline__ void cpa16(uint32_t dst, const void* src) {
    asm volatile("cp.async.cg.shared.global [%0], [%1], 16;" :: "r"(dst), "l"(src));
}
#define CP_COMMIT() asm volatile("cp.async.commit_group;" ::: "memory")
#define CP_WAIT(n)  asm volatile("cp.async.wait_group %0;" :: "n"(n) : "memory")

__device__ __forceinline__ void ldmx4(uint32_t* d, uint32_t addr) {
    asm volatile("ldmatrix.sync.aligned.m8n8.x4.shared.b16 {%0,%1,%2,%3}, [%4];"
                 : "=r"(d[0]), "=r"(d[1]), "=r"(d[2]), "=r"(d[3]) : "r"(addr));
}
__device__ __forceinline__ void mma16816(float* C, const uint32_t* A, uint32_t b0, uint32_t b1) {
    asm volatile(
        "mma.sync.aligned.m16n8k16.row.col.f32.bf16.bf16.f32 "
        "{%0,%1,%2,%3}, {%4,%5,%6,%7}, {%8,%9}, {%0,%1,%2,%3};"
        : "+f"(C[0]), "+f"(C[1]), "+f"(C[2]), "+f"(C[3])
        : "r"(A[0]), "r"(A[1]), "r"(A[2]), "r"(A[3]), "r"(b0), "r"(b1));
}
#define SW128(x) ((x) ^ (((x) >> 3) & 0x70))

// ---------------- edge-index dtype probe ----------------
__global__ void probe_kernel(const void* ei) {
    __shared__ int ok;
    if (threadIdx.x == 0) ok = 1;
    __syncthreads();
    long long v = ((const long long*)ei)[threadIdx.x];
    if (v < 0 || v >= (long long)N_NODES) atomicExch(&ok, 0);
    __syncthreads();
    if (threadIdx.x == 0) g_is64 = ok;
}
__device__ __forceinline__ int load_idx(const void* ei, long long pos) {
    return g_is64 ? (int)((const long long*)ei)[pos] : ((const int*)ei)[pos];
}

// ---------------- CSR build ----------------
__global__ void zero_kernel() {
    int i = blockIdx.x * blockDim.x + threadIdx.x;
    if (i < N_NODES) { g_deg[i] = 0; g_cursor[i] = 0; }
}
__global__ void hist_kernel(const void* ei) {
    int e = blockIdx.x * blockDim.x + threadIdx.x;
    if (e >= N_EDGES) return;
    atomicAdd(&g_deg[load_idx(ei, (long long)N_EDGES + e)], 1);
}
__global__ void scan_blocks() {
    __shared__ int wsum[32];
    int tid = threadIdx.x, lane = tid & 31, wid = tid >> 5;
    int i = blockIdx.x * 1024 + tid;
    int v = (i < N_NODES) ? g_deg[i] : 0;
    int x = v;
#pragma unroll
    for (int off = 1; off < 32; off <<= 1) {
        int t = __shfl_up_sync(0xffffffffu, x, off);
        if (lane >= off) x += t;
    }
    if (lane == 31) wsum[wid] = x;
    __syncthreads();
    if (wid == 0) {
        int s = wsum[lane];
#pragma unroll
        for (int off = 1; off < 32; off <<= 1) {
            int t = __shfl_up_sync(0xffffffffu, s, off);
            if (lane >= off) s += t;
        }
        wsum[lane] = s;
    }
    __syncthreads();
    int excl = x - v + ((wid > 0) ? wsum[wid - 1] : 0);
    if (i < N_NODES) g_rowptr[i] = excl;
    if (tid == 0) g_bsum[blockIdx.x] = wsum[31];
}
__global__ void scan_bsums() {
    __shared__ int s2[2];
    int tid = threadIdx.x, lane = tid & 31, wid = tid >> 5;
    int v = (tid < SCAN_NB) ? g_bsum[tid] : 0;
    int x = v;
#pragma unroll
    for (int off = 1; off < 32; off <<= 1) {
        int t = __shfl_up_sync(0xffffffffu, x, off);
        if (lane >= off) x += t;
    }
    if (lane == 31) s2[wid] = x;
    __syncthreads();
    int excl = x - v + ((wid > 0) ? s2[0] : 0);
    if (tid < SCAN_NB) g_boff[tid] = excl;
    if (tid == 0) g_rowptr[N_NODES] = N_EDGES;
}
__global__ void scan_add() {
    int i = blockIdx.x * 1024 + threadIdx.x;
    if (blockIdx.x > 0 && i < N_NODES) g_rowptr[i] += g_boff[blockIdx.x];
}
__global__ void fill_kernel(const void* ei, const float* __restrict__ ew) {
    int e = blockIdx.x * blockDim.x + threadIdx.x;
    if (e >= N_EDGES) return;
    int src = load_idx(ei, e);
    int dst = load_idx(ei, (long long)N_EDGES + e);
    int p = g_rowptr[dst] + atomicAdd(&g_cursor[dst], 1);
    g_csr_src[p] = src;
    g_csr_w[p]   = ew[e];
}

// ---------------- fp32 -> bf16 hi/lo split of emb ----------------
__global__ void conv_hilo(const float* __restrict__ x) {
    int i = blockIdx.x * blockDim.x + threadIdx.x;      // over N_NODES*HID/4
    if (i >= N_NODES * HID / 4) return;
    float4 v = ((const float4*)x)[i];
    float f[4] = {v.x, v.y, v.z, v.w};
    __align__(8) __nv_bfloat16 h[4], l[4];
#pragma unroll
    for (int j = 0; j < 4; j++) {
        h[j] = __float2bfloat16_rn(f[j]);
        l[j] = __float2bfloat16_rn(f[j] - __bfloat162float(h[j]));
    }
    ((uint2*)g_A1hi)[i] = *(uint2*)h;
    ((uint2*)g_A1lo)[i] = *(uint2*)l;
}

// ---------------- weight transpose + split: Wt[n][k] = W[k][n] ----------------
template <int LAYER>
__global__ void conv_wt(const float* __restrict__ Wa, const float* __restrict__ Wb) {
    constexpr int NTOT = (LAYER == 1) ? 512 : 256;
    constexpr int NH   = (LAYER == 1) ? 256 : 128;
    __nv_bfloat16* thi = (LAYER == 1) ? g_Wt1hi : g_Wt2hi;
    __nv_bfloat16* tlo = (LAYER == 1) ? g_Wt1lo : g_Wt2lo;
    int idx = blockIdx.x * blockDim.x + threadIdx.x;    // over NTOT*256
    if (idx >= NTOT * 256) return;
    int n = idx >> 8, k = idx & 255;
    float v = (n < NH) ? Wa[(size_t)k * NH + n] : Wb[(size_t)k * NH + (n - NH)];
    __nv_bfloat16 h = __float2bfloat16_rn(v);
    thi[idx] = h;
    tlo[idx] = __float2bfloat16_rn(v - __bfloat162float(h));
}

// ---------------- mma.sync bf16 split GEMM ----------------
// D[row0:+128][bn0:+128] = A[.,256] @ Wt[bn0:+128, 256]^T  via hi*hi+hi*lo+lo*hi
// CTA 128x128, 8 warps (warp tile 64x32), K-chunks of 32, cp.async double buffer.
// __launch_bounds__(256,2): 2 CTAs/SM for latency hiding; inner loop ordered to
// keep peak live registers ~100 (B frags resident, A frags streamed per-fm).
#define GBUF 32768
#define GSM_TOTAL (2 * GBUF)

template <int LAYER>
__global__ void __launch_bounds__(256, 2) gemm_mma() {
    const __nv_bfloat16* __restrict__ Ahi = (LAYER == 1) ? g_A1hi : g_h1hi;
    const __nv_bfloat16* __restrict__ Alo = (LAYER == 1) ? g_A1lo : g_h1lo;
    const __nv_bfloat16* __restrict__ Bhi = (LAYER == 1) ? g_Wt1hi : g_Wt2hi;
    const __nv_bfloat16* __restrict__ Blo = (LAYER == 1) ? g_Wt1lo : g_Wt2lo;

    const int bn0 = blockIdx.y * 128;
    float* __restrict__ out;
    int ostride, ocol0;
    if (LAYER == 1) {
        out = (bn0 < 256) ? g_T1l : g_T1r;
        ostride = 256; ocol0 = bn0 & 255;
    } else {
        out = (bn0 == 0) ? g_T2l : g_T2r;
        ostride = 128; ocol0 = 0;
    }

    extern __shared__ char smem[];
    uint32_t sb = smem_u32(smem);
    int tid = threadIdx.x, wid = tid >> 5, lane = tid & 31;
    int wm = (wid & 1) * 64, wn = (wid >> 1) * 32;
    int row0 = blockIdx.x * 128;

    float acc[4][4][4];
#pragma unroll
    for (int a = 0; a < 4; a++)
#pragma unroll
        for (int b = 0; b < 4; b++)
#pragma unroll
            for (int c = 0; c < 4; c++) acc[a][b][c] = 0.f;

    auto issue = [&](int kc) {
        uint32_t bb = sb + (uint32_t)(kc & 1) * GBUF;
#pragma unroll
        for (int i = 0; i < 2; i++) {
            int u = tid + i * 256;          // 0..511
            int r = u >> 2, c4 = u & 3;
            uint32_t d = SW128((uint32_t)(r * 64 + c4 * 16));
            size_t goA = (size_t)(row0 + r) * 256 + kc * 32 + c4 * 8;
            size_t goB = (size_t)(bn0 + r) * 256 + kc * 32 + c4 * 8;
            cpa16(bb + d,          Ahi + goA);
            cpa16(bb + 8192 + d,   Alo + goA);
            cpa16(bb + 16384 + d,  Bhi + goB);
            cpa16(bb + 24576 + d,  Blo + goB);
        }
        CP_COMMIT();
    };

    int lrow8 = ((lane >> 3) & 1) * 8 + (lane & 7);
    int lkoff = (lane >> 4);

    issue(0);
    for (int kc = 0; kc < 8; kc++) {
        if (kc + 1 < 8) { issue(kc + 1); CP_WAIT(1); } else { CP_WAIT(0); }
        __syncthreads();
        uint32_t bb = sb + (uint32_t)(kc & 1) * GBUF;
        uint32_t aH = bb, aL = bb + 8192, bH = bb + 16384, bL = bb + 24576;
#pragma unroll
        for (int k16 = 0; k16 < 2; k16++) {
            // B fragments resident for the whole k16 step
            uint32_t bh[2][4], bl[2][4];
#pragma unroll
            for (int g = 0; g < 2; g++) {
                int row = wn + g * 16 + lrow8;
                uint32_t bd = SW128((uint32_t)(row * 64 + (k16 * 2 + lkoff) * 16));
                ldmx4(bh[g], bH + bd);
                ldmx4(bl[g], bL + bd);
            }
            // stream A fragments per fm to bound live registers
#pragma unroll
            for (int fm = 0; fm < 4; fm++) {
                uint32_t ah[4], al[4];
                int row = wm + fm * 16 + lrow8;
                uint32_t ad = SW128((uint32_t)(row * 64 + (k16 * 2 + lkoff) * 16));
                ldmx4(ah, aH + ad);
                ldmx4(al, aL + ad);
#pragma unroll
                for (int fn = 0; fn < 4; fn++) {
                    int g = fn >> 1, p = fn & 1;
                    mma16816(acc[fm][fn], ah, bh[g][p], bh[g][p + 2]);  // hi*hi
                    mma16816(acc[fm][fn], ah, bl[g][p], bl[g][p + 2]);  // hi*lo
                    mma16816(acc[fm][fn], al, bh[g][p], bh[g][p + 2]);  // lo*hi
                }
            }
        }
        __syncthreads();
    }

#pragma unroll
    for (int fm = 0; fm < 4; fm++) {
        int r = row0 + wm + fm * 16 + (lane >> 2);
#pragma unroll
        for (int fn = 0; fn < 4; fn++) {
            int c = ocol0 + wn + fn * 8 + (lane & 3) * 2;
            if (r < N_NODES)
                *(float2*)(out + (size_t)r * ostride + c) =
                    make_float2(acc[fm][fn][0], acc[fm][fn][1]);
            if (r + 8 < N_NODES)
                *(float2*)(out + (size_t)(r + 8) * ostride + c) =
                    make_float2(acc[fm][fn][2], acc[fm][fn][3]);
        }
    }
}

// ---------------- AGG1: h1 = relu(meanagg(T1l) + T1r + b1) -> bf16 hi/lo ----------------
__device__ __forceinline__ void split_store4(__nv_bfloat16* hi, __nv_bfloat16* lo, float4 v) {
    float f[4] = {v.x, v.y, v.z, v.w};
    __align__(8) __nv_bfloat16 h[4], l[4];
#pragma unroll
    for (int i = 0; i < 4; i++) {
        h[i] = __float2bfloat16_rn(f[i]);
        l[i] = __float2bfloat16_rn(f[i] - __bfloat162float(h[i]));
    }
    *(uint2*)hi = *(uint2*)h;
    *(uint2*)lo = *(uint2*)l;
}

__global__ void agg1_kernel(const float* __restrict__ b1) {
    int gw = (blockIdx.x * blockDim.x + threadIdx.x) >> 5;
    int lane = threadIdx.x & 31;
    if (gw >= N_NODES) return;
    int beg = g_rowptr[gw], end = g_rowptr[gw + 1];
    float4 a0 = make_float4(0.f, 0.f, 0.f, 0.f);
    float4 a1 = make_float4(0.f, 0.f, 0.f, 0.f);
    int i = beg;
    for (; i + 1 < end; i += 2) {
        int   s0 = g_csr_src[i], s1 = g_csr_src[i + 1];
        float w0 = g_csr_w[i],   w1 = g_csr_w[i + 1];
        const float4* r0 = (const float4*)(g_T1l + (size_t)s0 * HID);
        const float4* r1 = (const float4*)(g_T1l + (size_t)s1 * HID);
        float4 u0 = r0[lane], u1 = r0[lane + 32];
        float4 v0 = r1[lane], v1 = r1[lane + 32];
        a0.x += u0.x * w0; a0.y += u0.y * w0; a0.z += u0.z * w0; a0.w += u0.w * w0;
        a1.x += u1.x * w0; a1.y += u1.y * w0; a1.z += u1.z * w0; a1.w += u1.w * w0;
        a0.x += v0.x * w1; a0.y += v0.y * w1; a0.z += v0.z * w1; a0.w += v0.w * w1;
        a1.x += v1.x * w1; a1.y += v1.y * w1; a1.z += v1.z * w1; a1.w += v1.w * w1;
    }
    if (i < end) {
        int   s = g_csr_src[i];
        float w = g_csr_w[i];
        const float4* r = (const float4*)(g_T1l + (size_t)s * HID);
        float4 u0 = r[lane], u1 = r[lane + 32];
        a0.x += u0.x * w; a0.y += u0.y * w; a0.z += u0.z * w; a0.w += u0.w * w;
        a1.x += u1.x * w; a1.y += u1.y * w; a1.z += u1.z * w; a1.w += u1.w * w;
    }
    float inv = 1.0f / fmaxf((float)(end - beg), 1.0f);
    const float4* tr = (const float4*)(g_T1r + (size_t)gw * HID);
    float4 t0 = tr[lane], t1 = tr[lane + 32];
    const float4* bb = (const float4*)b1;
    float4 c0 = bb[lane], c1 = bb[lane + 32];
    float4 o0, o1;
    o0.x = fmaxf(a0.x * inv + t0.x + c0.x, 0.f);
    o0.y = fmaxf(a0.y * inv + t0.y + c0.y, 0.f);
    o0.z = fmaxf(a0.z * inv + t0.z + c0.z, 0.f);
    o0.w = fmaxf(a0.w * inv + t0.w + c0.w, 0.f);
    o1.x = fmaxf(a1.x * inv + t1.x + c1.x, 0.f);
    o1.y = fmaxf(a1.y * inv + t1.y + c1.y, 0.f);
    o1.z = fmaxf(a1.z * inv + t1.z + c1.z, 0.f);
    o1.w = fmaxf(a1.w * inv + t1.w + c1.w, 0.f);
    split_store4(g_h1hi + (size_t)gw * HID + lane * 4,
                 g_h1lo + (size_t)gw * HID + lane * 4, o0);
    split_store4(g_h1hi + (size_t)gw * HID + 128 + lane * 4,
                 g_h1lo + (size_t)gw * HID + 128 + lane * 4, o1);
}

// ---------------- AGG2: out = meanagg(T2l) + T2r + b2 ----------------
__global__ void agg2_kernel(const float* __restrict__ b2, float* __restrict__ out) {
    int gw = (blockIdx.x * blockDim.x + threadIdx.x) >> 5;
    int lane = threadIdx.x & 31;
    if (gw >= N_NODES) return;
    int beg = g_rowptr[gw], end = g_rowptr[gw + 1];
    float4 a = make_float4(0.f, 0.f, 0.f, 0.f);
    int i = beg;
    for (; i + 3 < end; i += 4) {
        int s0 = g_csr_src[i], s1 = g_csr_src[i + 1], s2 = g_csr_src[i + 2], s3 = g_csr_src[i + 3];
        float w0 = g_csr_w[i], w1 = g_csr_w[i + 1], w2 = g_csr_w[i + 2], w3 = g_csr_w[i + 3];
        float4 u0 = ((const float4*)(g_T2l + (size_t)s0 * EMB))[lane];
        float4 u1 = ((const float4*)(g_T2l + (size_t)s1 * EMB))[lane];
        float4 u2 = ((const float4*)(g_T2l + (size_t)s2 * EMB))[lane];
        float4 u3 = ((const float4*)(g_T2l + (size_t)s3 * EMB))[lane];
        a.x += u0.x * w0 + u1.x * w1 + u2.x * w2 + u3.x * w3;
        a.y += u0.y * w0 + u1.y * w1 + u2.y * w2 + u3.y * w3;
        a.z += u0.z * w0 + u1.z * w1 + u2.z * w2 + u3.z * w3;
        a.w += u0.w * w0 + u1.w * w1 + u2.w * w2 + u3.w * w3;
    }
    for (; i < end; i++) {
        int s = g_csr_src[i];
        float w = g_csr_w[i];
        float4 u = ((const float4*)(g_T2l + (size_t)s * EMB))[lane];
        a.x += u.x * w; a.y += u.y * w; a.z += u.z * w; a.w += u.w * w;
    }
    float inv = 1.0f / fmaxf((float)(end - beg), 1.0f);
    float4 t = ((const float4*)(g_T2r + (size_t)gw * EMB))[lane];
    float4 c = ((const float4*)b2)[lane];
    float4 o;
    o.x = a.x * inv + t.x + c.x;
    o.y = a.y * inv + t.y + c.y;
    o.z = a.z * inv + t.z + c.z;
    o.w = a.w * inv + t.w + c.w;
    ((float4*)(out + (size_t)gw * EMB))[lane] = o;
}

// ---------------- streams/events for intra-graph concurrency ----------------
struct ForkCtx {
    cudaStream_t side = nullptr;
    cudaEvent_t  ev0 = nullptr, ev1 = nullptr;
    bool ok = false;
    ForkCtx() {
        if (cudaStreamCreateWithFlags(&side, cudaStreamNonBlocking) == cudaSuccess &&
            cudaEventCreateWithFlags(&ev0, cudaEventDisableTiming) == cudaSuccess &&
            cudaEventCreateWithFlags(&ev1, cudaEventDisableTiming) == cudaSuccess)
            ok = true;
    }
};
static ForkCtx g_fork;

// ---------------- launch ----------------
extern "C" void kernel_launch(void* const* d_in, const int* in_sizes, int n_in,
                              void* d_out, int out_size) {
    const void*  ei  = d_in[1];
    const float* ew  = (const float*)d_in[2];
    const float* emb = (const float*)d_in[3];
    const float* W1l = (const float*)d_in[4];
    const float* W1r = (const float*)d_in[5];
    const float* b1  = (const float*)d_in[6];
    const float* W2l = (const float*)d_in[7];
    const float* W2r = (const float*)d_in[8];
    const float* b2  = (const float*)d_in[9];
    float* out = (float*)d_out;

    static bool attr_done = false;
    if (!attr_done) {
        cudaFuncSetAttribute(gemm_mma<1>, cudaFuncAttributeMaxDynamicSharedMemorySize, GSM_TOTAL);
        cudaFuncSetAttribute(gemm_mma<2>, cudaFuncAttributeMaxDynamicSharedMemorySize, GSM_TOTAL);
        attr_done = true;
    }

    if (g_fork.ok) {
        cudaStream_t S = g_fork.side;
        cudaEventRecord(g_fork.ev0, 0);
        cudaStreamWaitEvent(S, g_fork.ev0, 0);

        // main stream: conversions + layer-1 GEMM (independent of CSR)
        conv_hilo<<<(N_NODES * HID / 4 + 255) / 256, 256>>>(emb);
        conv_wt<1><<<(512 * 256 + 255) / 256, 256>>>(W1l, W1r);
        conv_wt<2><<<(256 * 256 + 255) / 256, 256>>>(W2l, W2r);
        { dim3 g(M_TILES, 4); gemm_mma<1><<<g, 256, GSM_TOTAL>>>(); }

        // side stream: CSR build
        probe_kernel<<<1, 256, 0, S>>>(ei);
        zero_kernel<<<(N_NODES + 255) / 256, 256, 0, S>>>();
        hist_kernel<<<(N_EDGES + 255) / 256, 256, 0, S>>>(ei);
        scan_blocks<<<SCAN_NB, 1024, 0, S>>>();
        scan_bsums<<<1, 64, 0, S>>>();
        scan_add<<<SCAN_NB, 1024, 0, S>>>();
        fill_kernel<<<(N_EDGES + 255) / 256, 256, 0, S>>>(ei, ew);

        cudaEventRecord(g_fork.ev1, S);
        cudaStreamWaitEvent(0, g_fork.ev1, 0);

        agg1_kernel<<<(N_NODES * 32 + 255) / 256, 256>>>(b1);
        { dim3 g(M_TILES, 2); gemm_mma<2><<<g, 256, GSM_TOTAL>>>(); }
        agg2_kernel<<<(N_NODES * 32 + 255) / 256, 256>>>(b2, out);
    } else {
        probe_kernel<<<1, 256>>>(ei);
        zero_kernel<<<(N_NODES + 255) / 256, 256>>>();
        hist_kernel<<<(N_EDGES + 255) / 256, 256>>>(ei);
        scan_blocks<<<SCAN_NB, 1024>>>();
        scan_bsums<<<1, 64>>>();
        scan_add<<<SCAN_NB, 1024>>>();
        fill_kernel<<<(N_EDGES + 255) / 256, 256>>>(ei, ew);
        conv_hilo<<<(N_NODES * HID / 4 + 255) / 256, 256>>>(emb);
        conv_wt<1><<<(512 * 256 + 255) / 256, 256>>>(W1l, W1r);
        conv_wt<2><<<(256 * 256 + 255) / 256, 256>>>(W2l, W2r);
        { dim3 g(M_TILES, 4); gemm_mma<1><<<g, 256, GSM_TOTAL>>>(); }
        agg1_kernel<<<(N_NODES * 32 + 255) / 256, 256>>>(b1);
        { dim3 g(M_TILES, 2); gemm_mma<2><<<g, 256, GSM_TOTAL>>>(); }
        agg2_kernel<<<(N_NODES * 32 + 255) / 256, 256>>>(b2, out);
    }
}